// round 4
// baseline (speedup 1.0000x reference)
#include <cuda_runtime.h>
#include <math.h>

#define NN 100000
#define NE 1600000
#define DF 128
#define NG 512
#define DH 256
#define SB ((NN + 255) / 256)   // 391 scan blocks

// ------------------- scratch (__device__ globals; no allocation) -------------------
static __device__ int   g_cnt[NN];
static __device__ int   g_wptr[NN];
static __device__ int   g_rowptr[NN + 1];
static __device__ int   g_bsum[512];
static __device__ int   g_boff[512];
static __device__ int   g_col[NE];
static __device__ float g_dinv[NN];
static __device__ __align__(16) float g_x0[(size_t)NN * DF];
static __device__ __align__(16) float g_x1[(size_t)NN * DF];
static __device__ __align__(16) float g_h [(size_t)NN * DF];
static __device__ __align__(16) float g_Wmod[DF * DF];
static __device__ __align__(16) float g_dvec[DF];
static __device__ float g_bnsum[DF];
static __device__ float g_bnsq[DF];
static __device__ float g_affa[DF];
static __device__ float g_affc[DF];
static __device__ __align__(16) float g_pool[NG * DF];
static __device__ float g_gcnt[NG];
static __device__ float g_h0[NG * DH];
static __device__ float g_h1[NG * DH];
static __device__ float g_s0[DH];
static __device__ float g_q0[DH];
static __device__ float g_ha[DH];
static __device__ float g_hc[DH];

// ------------------- utility -------------------
__global__ void k_zero_f(float* p, int n) {
    int i = blockIdx.x * blockDim.x + threadIdx.x;
    if (i < n) p[i] = 0.f;
}
__global__ void k_zero_i(int* p, int n) {
    int i = blockIdx.x * blockDim.x + threadIdx.x;
    if (i < n) p[i] = 0;
}

// ------------------- CSR build -------------------
__global__ void k_hist(const int* __restrict__ dst) {
    int e = blockIdx.x * blockDim.x + threadIdx.x;
    if (e < NE) atomicAdd(&g_cnt[dst[e]], 1);
}
__global__ void k_dinv() {
    int v = blockIdx.x * blockDim.x + threadIdx.x;
    if (v < NN) g_dinv[v] = rsqrtf((float)g_cnt[v] + 1.0f);
}
__global__ void __launch_bounds__(256) k_scanA() {
    __shared__ int s[256];
    int t = threadIdx.x;
    int i = blockIdx.x * 256 + t;
    int v = (i < NN) ? g_cnt[i] : 0;
    s[t] = v;
    __syncthreads();
#pragma unroll
    for (int off = 1; off < 256; off <<= 1) {
        int u = (t >= off) ? s[t - off] : 0;
        __syncthreads();
        s[t] += u;
        __syncthreads();
    }
    if (i < NN) g_rowptr[i] = s[t] - v;
    if (t == 255) g_bsum[blockIdx.x] = s[255];
}
__global__ void __launch_bounds__(512) k_scanB() {
    __shared__ int s[512];
    int t = threadIdx.x;
    int v = (t < SB) ? g_bsum[t] : 0;
    s[t] = v;
    __syncthreads();
#pragma unroll
    for (int off = 1; off < 512; off <<= 1) {
        int u = (t >= off) ? s[t - off] : 0;
        __syncthreads();
        s[t] += u;
        __syncthreads();
    }
    g_boff[t] = s[t] - v;
    if (t == 0) g_rowptr[NN] = NE;
}
__global__ void __launch_bounds__(256) k_scanC() {
    int i = blockIdx.x * 256 + threadIdx.x;
    if (i < NN) {
        int r = g_rowptr[i] + g_boff[blockIdx.x];
        g_rowptr[i] = r;
        g_wptr[i]   = r;
    }
}
__global__ void k_fill(const int* __restrict__ src, const int* __restrict__ dst) {
    int e = blockIdx.x * blockDim.x + threadIdx.x;
    if (e < NE) {
        int v = dst[e];
        int pos = atomicAdd(&g_wptr[v], 1);
        g_col[pos] = src[e];
    }
}

// ------------------- SGEMM with packed f32x2 FMA -------------------
// C[M,128] = A[M,128] @ B[128,128] (+ dvec row)
// BM=128, BN=128, BK=8, TM=8, TN=8, 256 threads
__global__ void __launch_bounds__(256) k_sgemm(
    const float* __restrict__ A, const float* __restrict__ B,
    const float* __restrict__ dvec, float* __restrict__ C, int M)
{
    const int BM = 128, BN = 128, BK = 8, TM = 8;
    __shared__ __align__(16) float As[BK * BM];  // transposed: As[k][m]
    __shared__ __align__(16) float Bs[BK * BN];

    int tid  = threadIdx.x;
    int row0 = blockIdx.x * BM;
    int tr = tid / 16;            // 0..15
    int tc = tid % 16;            // 0..15

    // acc2[i][j] holds C[i][2j], C[i][2j+1] packed
    unsigned long long acc2[TM][4];
#pragma unroll
    for (int i = 0; i < TM; i++)
#pragma unroll
        for (int j = 0; j < 4; j++) acc2[i][j] = 0ull;

    int arow = tid >> 1;           // 0..127
    int acol = (tid & 1) * 4;      // 0 or 4
    int brow = tid >> 5;           // 0..7
    int bcol = (tid & 31) * 4;     // 0..124

    for (int kk = 0; kk < 128; kk += BK) {
        float4 av;
        if (row0 + arow < M)
            av = *(const float4*)(A + (size_t)(row0 + arow) * 128 + kk + acol);
        else
            av = make_float4(0.f, 0.f, 0.f, 0.f);
        As[(acol + 0) * BM + arow] = av.x;
        As[(acol + 1) * BM + arow] = av.y;
        As[(acol + 2) * BM + arow] = av.z;
        As[(acol + 3) * BM + arow] = av.w;

        float4 bv = *(const float4*)(B + (size_t)(kk + brow) * 128 + bcol);
        *(float4*)(Bs + brow * BN + bcol) = bv;
        __syncthreads();

#pragma unroll
        for (int k = 0; k < BK; k++) {
            float ra[TM];
            float4 ra0 = *(const float4*)(As + k * BM + tr * TM);
            float4 ra1 = *(const float4*)(As + k * BM + tr * TM + 4);
            ra[0] = ra0.x; ra[1] = ra0.y; ra[2] = ra0.z; ra[3] = ra0.w;
            ra[4] = ra1.x; ra[5] = ra1.y; ra[6] = ra1.z; ra[7] = ra1.w;

            ulonglong2 rb0 = *(const ulonglong2*)(Bs + k * BN + tc * 8);
            ulonglong2 rb1 = *(const ulonglong2*)(Bs + k * BN + tc * 8 + 4);
            unsigned long long bp[4] = {rb0.x, rb0.y, rb1.x, rb1.y};

#pragma unroll
            for (int i = 0; i < TM; i++) {
                unsigned long long ap;
                asm("mov.b64 %0, {%1, %1};" : "=l"(ap) : "f"(ra[i]));
#pragma unroll
                for (int j = 0; j < 4; j++)
                    asm("fma.rn.f32x2 %0, %1, %2, %0;"
                        : "+l"(acc2[i][j]) : "l"(ap), "l"(bp[j]));
            }
        }
        __syncthreads();
    }

    float dv[8];
#pragma unroll
    for (int j = 0; j < 8; j++) dv[j] = dvec ? dvec[tc * 8 + j] : 0.f;

#pragma unroll
    for (int i = 0; i < TM; i++) {
        int r = row0 + tr * TM + i;
        if (r < M) {
            float c[8];
#pragma unroll
            for (int j = 0; j < 4; j++) {
                float lo, hi;
                asm("mov.b64 {%0, %1}, %2;" : "=f"(lo), "=f"(hi) : "l"(acc2[i][j]));
                c[2 * j]     = lo + dv[2 * j];
                c[2 * j + 1] = hi + dv[2 * j + 1];
            }
            *(float4*)(C + (size_t)r * 128 + tc * 8)     = make_float4(c[0], c[1], c[2], c[3]);
            *(float4*)(C + (size_t)r * 128 + tc * 8 + 4) = make_float4(c[4], c[5], c[6], c[7]);
        }
    }
}

// ------------------- GCN aggregation + bias + relu + fused BN stats -------------------
__global__ void __launch_bounds__(256) k_agg(
    const float* __restrict__ h, const float* __restrict__ bias,
    float* __restrict__ xout)
{
    __shared__ float bs[DF], bq[DF];
    int tid = threadIdx.x;
    if (tid < DF) { bs[tid] = 0.f; bq[tid] = 0.f; }
    __syncthreads();

    int lane = tid & 31;
    int w    = tid >> 5;
    int warpId = blockIdx.x * (blockDim.x >> 5) + w;
    int nW     = gridDim.x * (blockDim.x >> 5);

    float4 bv = *(const float4*)(bias + lane * 4);
    float ls0 = 0, ls1 = 0, ls2 = 0, ls3 = 0;
    float lq0 = 0, lq1 = 0, lq2 = 0, lq3 = 0;

    for (int v = warpId; v < NN; v += nW) {
        float dv = g_dinv[v];
        float4 hv = *((const float4*)(h + (size_t)v * DF) + lane);
        float ax = hv.x * dv, ay = hv.y * dv, az = hv.z * dv, aw = hv.w * dv;

        int beg = g_rowptr[v], end = g_rowptr[v + 1];
        for (int e0 = beg; e0 < end; e0 += 32) {
            int idx = e0 + lane;
            int   sl = (idx < end) ? g_col[idx]  : 0;
            float dl = (idx < end) ? g_dinv[sl]  : 0.f;
            int m = end - e0; if (m > 32) m = 32;
            for (int j = 0; j < m; j++) {
                int   sj  = __shfl_sync(0xffffffffu, sl, j);
                float dsj = __shfl_sync(0xffffffffu, dl, j);
                float4 hs = *((const float4*)(h + (size_t)sj * DF) + lane);
                ax = fmaf(hs.x, dsj, ax);
                ay = fmaf(hs.y, dsj, ay);
                az = fmaf(hs.z, dsj, az);
                aw = fmaf(hs.w, dsj, aw);
            }
        }
        float ox = fmaxf(fmaf(ax, dv, bv.x), 0.f);
        float oy = fmaxf(fmaf(ay, dv, bv.y), 0.f);
        float oz = fmaxf(fmaf(az, dv, bv.z), 0.f);
        float ow = fmaxf(fmaf(aw, dv, bv.w), 0.f);
        *((float4*)(xout + (size_t)v * DF) + lane) = make_float4(ox, oy, oz, ow);
        ls0 += ox; lq0 += ox * ox;
        ls1 += oy; lq1 += oy * oy;
        ls2 += oz; lq2 += oz * oz;
        ls3 += ow; lq3 += ow * ow;
    }
    atomicAdd(&bs[lane * 4 + 0], ls0); atomicAdd(&bq[lane * 4 + 0], lq0);
    atomicAdd(&bs[lane * 4 + 1], ls1); atomicAdd(&bq[lane * 4 + 1], lq1);
    atomicAdd(&bs[lane * 4 + 2], ls2); atomicAdd(&bq[lane * 4 + 2], lq2);
    atomicAdd(&bs[lane * 4 + 3], ls3); atomicAdd(&bq[lane * 4 + 3], lq3);
    __syncthreads();
    if (tid < DF) {
        atomicAdd(&g_bnsum[tid], bs[tid]);
        atomicAdd(&g_bnsq[tid],  bq[tid]);
    }
}

// ------------------- BN affine params -------------------
__global__ void k_bnaff(const float* __restrict__ sum, const float* __restrict__ sq,
                        const float* __restrict__ gamma, const float* __restrict__ beta,
                        float* __restrict__ a, float* __restrict__ c,
                        int D, float invN)
{
    int j = blockIdx.x * blockDim.x + threadIdx.x;
    if (j >= D) return;
    float m   = sum[j] * invN;
    float var = sq[j] * invN - m * m;
    float aj  = gamma[j] * rsqrtf(var + 1e-5f);
    a[j] = aj;
    c[j] = beta[j] - aj * m;
}

// Wmod[k][j] = a[k] * W[k][j]
__global__ void k_wprep(const float* __restrict__ W) {
    int i = blockIdx.x * blockDim.x + threadIdx.x;
    if (i < DF * DF) g_Wmod[i] = g_affa[i >> 7] * W[i];
}
// d[j] = sum_k c[k] * W[k][j]
__global__ void k_dvec(const float* __restrict__ W) {
    int j = threadIdx.x;
    if (j < DF) {
        float s = 0.f;
        for (int k = 0; k < DF; k++) s = fmaf(g_affc[k], W[k * DF + j], s);
        g_dvec[j] = s;
    }
}

// ------------------- global_add_pool -------------------
__global__ void k_pool(const float* __restrict__ x, const int* __restrict__ batch) {
    int lane = threadIdx.x & 31;
    int w    = (blockIdx.x * blockDim.x + threadIdx.x) >> 5;
    int nW   = (gridDim.x * blockDim.x) >> 5;
    int C    = (NN + nW - 1) / nW;
    int beg = w * C;
    int end = beg + C; if (end > NN) end = NN;
    if (beg >= end) return;

    float a0 = 0, a1 = 0, a2 = 0, a3 = 0, cntf = 0;
    int cur = batch[beg];
    for (int v = beg; v < end; v++) {
        int g = batch[v];
        if (g != cur) {
            atomicAdd(&g_pool[cur * DF + lane * 4 + 0], a0);
            atomicAdd(&g_pool[cur * DF + lane * 4 + 1], a1);
            atomicAdd(&g_pool[cur * DF + lane * 4 + 2], a2);
            atomicAdd(&g_pool[cur * DF + lane * 4 + 3], a3);
            if (lane == 0) atomicAdd(&g_gcnt[cur], cntf);
            a0 = a1 = a2 = a3 = 0.f; cntf = 0.f; cur = g;
        }
        float4 xv = *((const float4*)(x + (size_t)v * DF) + lane);
        a0 += xv.x; a1 += xv.y; a2 += xv.z; a3 += xv.w; cntf += 1.f;
    }
    atomicAdd(&g_pool[cur * DF + lane * 4 + 0], a0);
    atomicAdd(&g_pool[cur * DF + lane * 4 + 1], a1);
    atomicAdd(&g_pool[cur * DF + lane * 4 + 2], a2);
    atomicAdd(&g_pool[cur * DF + lane * 4 + 3], a3);
    if (lane == 0) atomicAdd(&g_gcnt[cur], cntf);
}

// ------------------- head -------------------
__global__ void __launch_bounds__(256) k_hg0(const float* __restrict__ Wh0,
                                             const float* __restrict__ bh0) {
    __shared__ float sx[DF];
    int g = blockIdx.x, j = threadIdx.x;
    if (j < DF) sx[j] = g_affa[j] * g_pool[g * DF + j] + g_affc[j] * g_gcnt[g];
    __syncthreads();
    float acc = bh0[j];
#pragma unroll 8
    for (int k = 0; k < DF; k++) acc = fmaf(sx[k], Wh0[k * DH + j], acc);
    float v = fmaxf(acc, 0.f);
    g_h0[g * DH + j] = v;
    atomicAdd(&g_s0[j], v);
    atomicAdd(&g_q0[j], v * v);
}
__global__ void __launch_bounds__(256) k_hg1(const float* __restrict__ Wh1,
                                             const float* __restrict__ bh1) {
    __shared__ float sx[DH];
    int g = blockIdx.x, j = threadIdx.x;
    sx[j] = g_ha[j] * g_h0[g * DH + j] + g_hc[j];
    __syncthreads();
    float acc = bh1[j];
#pragma unroll 8
    for (int k = 0; k < DH; k++) acc = fmaf(sx[k], Wh1[k * DH + j], acc);
    float v = fmaxf(acc, 0.f);
    g_h1[g * DH + j] = v;
    atomicAdd(&g_s0[j], v);
    atomicAdd(&g_q0[j], v * v);
}
__global__ void __launch_bounds__(256) k_final(const float* __restrict__ Wout,
                                               const float* __restrict__ bout,
                                               float* __restrict__ out) {
    __shared__ float red[DH];
    int g = blockIdx.x, t = threadIdx.x;
    red[t] = (g_ha[t] * g_h1[g * DH + t] + g_hc[t]) * Wout[t];
    __syncthreads();
    for (int o = DH / 2; o > 0; o >>= 1) {
        if (t < o) red[t] += red[t + o];
        __syncthreads();
    }
    if (t == 0) out[g] = red[0] + bout[0];
}

// ------------------- launch -------------------
extern "C" void kernel_launch(void* const* d_in, const int* in_sizes, int n_in,
                              void* d_out, int out_size) {
    const float* x   = (const float*)d_in[0];
    const int*   ei  = (const int*)d_in[1];
    const int*   bat = (const int*)d_in[2];
    const float* Wc  = (const float*)d_in[3];
    const float* bc  = (const float*)d_in[4];
    const float* gc  = (const float*)d_in[5];
    const float* bec = (const float*)d_in[6];
    const float* Wh0 = (const float*)d_in[7];
    const float* bh0 = (const float*)d_in[8];
    const float* gh0 = (const float*)d_in[9];
    const float* beh0= (const float*)d_in[10];
    const float* Wh1 = (const float*)d_in[11];
    const float* bh1 = (const float*)d_in[12];
    const float* gh1 = (const float*)d_in[13];
    const float* beh1= (const float*)d_in[14];
    const float* Wout= (const float*)d_in[15];
    const float* bout= (const float*)d_in[16];
    float* out = (float*)d_out;

    const int* src = ei;
    const int* dst = ei + NE;

    float *p_x0, *p_x1, *p_h, *p_Wmod, *p_dvec, *p_bnsum, *p_bnsq;
    float *p_affa, *p_affc, *p_pool, *p_gcnt, *p_s0, *p_q0, *p_ha, *p_hc;
    int   *p_cnt;
    cudaGetSymbolAddress((void**)&p_x0,   g_x0);
    cudaGetSymbolAddress((void**)&p_x1,   g_x1);
    cudaGetSymbolAddress((void**)&p_h,    g_h);
    cudaGetSymbolAddress((void**)&p_Wmod, g_Wmod);
    cudaGetSymbolAddress((void**)&p_dvec, g_dvec);
    cudaGetSymbolAddress((void**)&p_bnsum,g_bnsum);
    cudaGetSymbolAddress((void**)&p_bnsq, g_bnsq);
    cudaGetSymbolAddress((void**)&p_affa, g_affa);
    cudaGetSymbolAddress((void**)&p_affc, g_affc);
    cudaGetSymbolAddress((void**)&p_pool, g_pool);
    cudaGetSymbolAddress((void**)&p_gcnt, g_gcnt);
    cudaGetSymbolAddress((void**)&p_s0,   g_s0);
    cudaGetSymbolAddress((void**)&p_q0,   g_q0);
    cudaGetSymbolAddress((void**)&p_ha,   g_ha);
    cudaGetSymbolAddress((void**)&p_hc,   g_hc);
    cudaGetSymbolAddress((void**)&p_cnt,  g_cnt);

    const int T = 256;
    const int gemmBlocks = (NN + 127) / 128;

    // ---- CSR build + degree ----
    k_zero_i<<<(NN + T - 1) / T, T>>>(p_cnt, NN);
    k_hist<<<(NE + T - 1) / T, T>>>(dst);
    k_dinv<<<(NN + T - 1) / T, T>>>();
    k_scanA<<<SB, 256>>>();
    k_scanB<<<1, 512>>>();
    k_scanC<<<SB, 256>>>();
    k_fill<<<(NE + T - 1) / T, T>>>(src, dst);

    // ---- conv layer 0 ----
    k_sgemm<<<gemmBlocks, T>>>(x, Wc, nullptr, p_h, NN);
    k_zero_f<<<1, DF>>>(p_bnsum, DF);
    k_zero_f<<<1, DF>>>(p_bnsq, DF);
    k_agg<<<2048, T>>>(p_h, bc, p_x0);
    k_bnaff<<<1, DF>>>(p_bnsum, p_bnsq, gc, bec, p_affa, p_affc, DF, 1.0f / NN);

    // ---- conv layer 1 (BN0 folded into GEMM) ----
    k_wprep<<<(DF * DF + T - 1) / T, T>>>(Wc + DF * DF);
    k_dvec<<<1, DF>>>(Wc + DF * DF);
    k_sgemm<<<gemmBlocks, T>>>(p_x0, p_Wmod, p_dvec, p_h, NN);
    k_zero_f<<<1, DF>>>(p_bnsum, DF);
    k_zero_f<<<1, DF>>>(p_bnsq, DF);
    k_agg<<<2048, T>>>(p_h, bc + DF, p_x1);
    k_bnaff<<<1, DF>>>(p_bnsum, p_bnsq, gc + DF, bec + DF, p_affa, p_affc, DF, 1.0f / NN);

    // ---- conv layer 2 ----
    k_wprep<<<(DF * DF + T - 1) / T, T>>>(Wc + 2 * DF * DF);
    k_dvec<<<1, DF>>>(Wc + 2 * DF * DF);
    k_sgemm<<<gemmBlocks, T>>>(p_x1, p_Wmod, p_dvec, p_h, NN);
    k_zero_f<<<1, DF>>>(p_bnsum, DF);
    k_zero_f<<<1, DF>>>(p_bnsq, DF);
    k_agg<<<2048, T>>>(p_h, bc + 2 * DF, p_x0);
    k_bnaff<<<1, DF>>>(p_bnsum, p_bnsq, gc + 2 * DF, bec + 2 * DF, p_affa, p_affc, DF, 1.0f / NN);

    // ---- pool (BN2 applied in head gemm0 via g_affa/g_affc) ----
    k_zero_f<<<(NG * DF + T - 1) / T, T>>>(p_pool, NG * DF);
    k_zero_f<<<(NG + T - 1) / T, T>>>(p_gcnt, NG);
    k_pool<<<128, T>>>(p_x0, bat);

    // ---- head ----
    k_zero_f<<<1, DH>>>(p_s0, DH);
    k_zero_f<<<1, DH>>>(p_q0, DH);
    k_hg0<<<NG, DH>>>(Wh0, bh0);
    k_bnaff<<<1, DH>>>(p_s0, p_q0, gh0, beh0, p_ha, p_hc, DH, 1.0f / NG);
    k_zero_f<<<1, DH>>>(p_s0, DH);
    k_zero_f<<<1, DH>>>(p_q0, DH);
    k_hg1<<<NG, DH>>>(Wh1, bh1);
    k_bnaff<<<1, DH>>>(p_s0, p_q0, gh1, beh1, p_ha, p_hc, DH, 1.0f / NG);
    k_final<<<NG, DH>>>(Wout, bout, out);
}

// round 5
// speedup vs baseline: 1.0790x; 1.0790x over previous
#include <cuda_runtime.h>
#include <math.h>

#define NN 100000
#define NE 1600000
#define DF 128
#define NG 512
#define DH 256
#define SB ((NN + 255) / 256)   // 391 scan blocks

// ------------------- scratch (__device__ globals; no allocation) -------------------
static __device__ int   g_cnt[NN];
static __device__ int   g_wptr[NN];
static __device__ int   g_rowptr[NN + 1];
static __device__ int   g_bsum[512];
static __device__ int   g_boff[512];
static __device__ int   g_col[NE];
static __device__ float g_dinv[NN];
static __device__ __align__(16) float g_x0[(size_t)NN * DF];
static __device__ __align__(16) float g_x1[(size_t)NN * DF];
static __device__ __align__(16) float g_h [(size_t)NN * DF];
static __device__ __align__(16) float g_Wmod[DF * DF];
static __device__ __align__(16) float g_dvec[DF];
static __device__ float g_bnsum[DF];
static __device__ float g_bnsq[DF];
static __device__ float g_affa[DF];
static __device__ float g_affc[DF];
static __device__ __align__(16) float g_pool[NG * DF];
static __device__ float g_gcnt[NG];
static __device__ float g_h0[NG * DH];
static __device__ float g_h1[NG * DH];
static __device__ float g_s0[DH];
static __device__ float g_q0[DH];
static __device__ float g_ha[DH];
static __device__ float g_hc[DH];

// ------------------- utility -------------------
__global__ void k_zero_f(float* p, int n) {
    int i = blockIdx.x * blockDim.x + threadIdx.x;
    if (i < n) p[i] = 0.f;
}
__global__ void k_zero_i(int* p, int n) {
    int i = blockIdx.x * blockDim.x + threadIdx.x;
    if (i < n) p[i] = 0;
}

// ------------------- CSR build -------------------
__global__ void k_hist(const int* __restrict__ dst) {
    int e = blockIdx.x * blockDim.x + threadIdx.x;
    if (e < NE) atomicAdd(&g_cnt[dst[e]], 1);
}
__global__ void k_dinv() {
    int v = blockIdx.x * blockDim.x + threadIdx.x;
    if (v < NN) g_dinv[v] = rsqrtf((float)g_cnt[v] + 1.0f);
}
__global__ void __launch_bounds__(256) k_scanA() {
    __shared__ int s[256];
    int t = threadIdx.x;
    int i = blockIdx.x * 256 + t;
    int v = (i < NN) ? g_cnt[i] : 0;
    s[t] = v;
    __syncthreads();
#pragma unroll
    for (int off = 1; off < 256; off <<= 1) {
        int u = (t >= off) ? s[t - off] : 0;
        __syncthreads();
        s[t] += u;
        __syncthreads();
    }
    if (i < NN) g_rowptr[i] = s[t] - v;
    if (t == 255) g_bsum[blockIdx.x] = s[255];
}
__global__ void __launch_bounds__(512) k_scanB() {
    __shared__ int s[512];
    int t = threadIdx.x;
    int v = (t < SB) ? g_bsum[t] : 0;
    s[t] = v;
    __syncthreads();
#pragma unroll
    for (int off = 1; off < 512; off <<= 1) {
        int u = (t >= off) ? s[t - off] : 0;
        __syncthreads();
        s[t] += u;
        __syncthreads();
    }
    g_boff[t] = s[t] - v;
    if (t == 0) g_rowptr[NN] = NE;
}
__global__ void __launch_bounds__(256) k_scanC() {
    int i = blockIdx.x * 256 + threadIdx.x;
    if (i < NN) {
        int r = g_rowptr[i] + g_boff[blockIdx.x];
        g_rowptr[i] = r;
        g_wptr[i]   = r;
    }
}
__global__ void k_fill(const int* __restrict__ src, const int* __restrict__ dst) {
    int e = blockIdx.x * blockDim.x + threadIdx.x;
    if (e < NE) {
        int v = dst[e];
        int pos = atomicAdd(&g_wptr[v], 1);
        g_col[pos] = src[e];
    }
}

// ------------------- SGEMM: C[M,128] = dinv[r] * (A[M,128] @ B[128,128] + dvec) ---------
// BM=128, BN=128, BK=8, TM=8, TN=8, 256 threads (plain FFMA — R2 version + dinv epilogue)
__global__ void __launch_bounds__(256) k_sgemm(
    const float* __restrict__ A, const float* __restrict__ B,
    const float* __restrict__ dvec, const float* __restrict__ dinv,
    float* __restrict__ C, int M)
{
    const int BM = 128, BN = 128, BK = 8, TM = 8, TN = 8;
    __shared__ __align__(16) float As[BK * BM];  // transposed: As[k][m]
    __shared__ __align__(16) float Bs[BK * BN];

    int tid  = threadIdx.x;
    int row0 = blockIdx.x * BM;
    int tr = tid / 16;            // 0..15
    int tc = tid % 16;            // 0..15

    float acc[TM][TN];
#pragma unroll
    for (int i = 0; i < TM; i++)
#pragma unroll
        for (int j = 0; j < TN; j++) acc[i][j] = 0.f;

    int arow = tid >> 1;           // 0..127
    int acol = (tid & 1) * 4;      // 0 or 4
    int brow = tid >> 5;           // 0..7
    int bcol = (tid & 31) * 4;     // 0..124

    for (int kk = 0; kk < 128; kk += BK) {
        float4 av;
        if (row0 + arow < M)
            av = *(const float4*)(A + (size_t)(row0 + arow) * 128 + kk + acol);
        else
            av = make_float4(0.f, 0.f, 0.f, 0.f);
        As[(acol + 0) * BM + arow] = av.x;
        As[(acol + 1) * BM + arow] = av.y;
        As[(acol + 2) * BM + arow] = av.z;
        As[(acol + 3) * BM + arow] = av.w;

        float4 bv = *(const float4*)(B + (size_t)(kk + brow) * 128 + bcol);
        *(float4*)(Bs + brow * BN + bcol) = bv;
        __syncthreads();

#pragma unroll
        for (int k = 0; k < BK; k++) {
            float ra[TM], rb[TN];
            float4 ra0 = *(const float4*)(As + k * BM + tr * TM);
            float4 ra1 = *(const float4*)(As + k * BM + tr * TM + 4);
            ra[0] = ra0.x; ra[1] = ra0.y; ra[2] = ra0.z; ra[3] = ra0.w;
            ra[4] = ra1.x; ra[5] = ra1.y; ra[6] = ra1.z; ra[7] = ra1.w;
            float4 rb0 = *(const float4*)(Bs + k * BN + tc * TN);
            float4 rb1 = *(const float4*)(Bs + k * BN + tc * TN + 4);
            rb[0] = rb0.x; rb[1] = rb0.y; rb[2] = rb0.z; rb[3] = rb0.w;
            rb[4] = rb1.x; rb[5] = rb1.y; rb[6] = rb1.z; rb[7] = rb1.w;
#pragma unroll
            for (int i = 0; i < TM; i++)
#pragma unroll
                for (int j = 0; j < TN; j++)
                    acc[i][j] = fmaf(ra[i], rb[j], acc[i][j]);
        }
        __syncthreads();
    }

    float dv[TN];
#pragma unroll
    for (int j = 0; j < TN; j++) dv[j] = dvec ? dvec[tc * TN + j] : 0.f;

#pragma unroll
    for (int i = 0; i < TM; i++) {
        int r = row0 + tr * TM + i;
        if (r < M) {
            float s = dinv[r];
            float4 o0 = make_float4(s * (acc[i][0] + dv[0]), s * (acc[i][1] + dv[1]),
                                    s * (acc[i][2] + dv[2]), s * (acc[i][3] + dv[3]));
            float4 o1 = make_float4(s * (acc[i][4] + dv[4]), s * (acc[i][5] + dv[5]),
                                    s * (acc[i][6] + dv[6]), s * (acc[i][7] + dv[7]));
            *(float4*)(C + (size_t)r * 128 + tc * TN)     = o0;
            *(float4*)(C + (size_t)r * 128 + tc * TN + 4) = o1;
        }
    }
}

// ------------------- GCN aggregation (h pre-scaled by dinv) + bias + relu + BN stats ----
// out[v] = relu(dinv[v] * (h'[v] + sum_src h'[src]) + bias)
__global__ void __launch_bounds__(256) k_agg(
    const float* __restrict__ h, const float* __restrict__ bias,
    float* __restrict__ xout)
{
    __shared__ float bs[DF], bq[DF];
    int tid = threadIdx.x;
    if (tid < DF) { bs[tid] = 0.f; bq[tid] = 0.f; }
    __syncthreads();

    int lane = tid & 31;
    int w    = tid >> 5;
    int warpId = blockIdx.x * (blockDim.x >> 5) + w;
    int nW     = gridDim.x * (blockDim.x >> 5);

    float4 bv = *(const float4*)(bias + lane * 4);
    float ls0 = 0, ls1 = 0, ls2 = 0, ls3 = 0;
    float lq0 = 0, lq1 = 0, lq2 = 0, lq3 = 0;

    for (int v = warpId; v < NN; v += nW) {
        float dv = g_dinv[v];
        float4 hv = *((const float4*)(h + (size_t)v * DF) + lane);  // self loop (pre-scaled)
        float ax = hv.x, ay = hv.y, az = hv.z, aw = hv.w;

        int beg = g_rowptr[v], end = g_rowptr[v + 1];
        int e0 = beg;
        // full 32-edge chunks
        for (; e0 + 32 <= end; e0 += 32) {
            int sl = g_col[e0 + lane];
#pragma unroll 4
            for (int j = 0; j < 32; j++) {
                int sj = __shfl_sync(0xffffffffu, sl, j);
                float4 hs = *((const float4*)(h + (size_t)sj * DF) + lane);
                ax += hs.x; ay += hs.y; az += hs.z; aw += hs.w;
            }
        }
        // tail
        if (e0 < end) {
            int m = end - e0;
            int sl = (e0 + lane < end) ? g_col[e0 + lane] : 0;
            for (int j = 0; j < m; j++) {
                int sj = __shfl_sync(0xffffffffu, sl, j);
                float4 hs = *((const float4*)(h + (size_t)sj * DF) + lane);
                ax += hs.x; ay += hs.y; az += hs.z; aw += hs.w;
            }
        }
        float ox = fmaxf(fmaf(ax, dv, bv.x), 0.f);
        float oy = fmaxf(fmaf(ay, dv, bv.y), 0.f);
        float oz = fmaxf(fmaf(az, dv, bv.z), 0.f);
        float ow = fmaxf(fmaf(aw, dv, bv.w), 0.f);
        *((float4*)(xout + (size_t)v * DF) + lane) = make_float4(ox, oy, oz, ow);
        ls0 += ox; lq0 += ox * ox;
        ls1 += oy; lq1 += oy * oy;
        ls2 += oz; lq2 += oz * oz;
        ls3 += ow; lq3 += ow * ow;
    }
    atomicAdd(&bs[lane * 4 + 0], ls0); atomicAdd(&bq[lane * 4 + 0], lq0);
    atomicAdd(&bs[lane * 4 + 1], ls1); atomicAdd(&bq[lane * 4 + 1], lq1);
    atomicAdd(&bs[lane * 4 + 2], ls2); atomicAdd(&bq[lane * 4 + 2], lq2);
    atomicAdd(&bs[lane * 4 + 3], ls3); atomicAdd(&bq[lane * 4 + 3], lq3);
    __syncthreads();
    if (tid < DF) {
        atomicAdd(&g_bnsum[tid], bs[tid]);
        atomicAdd(&g_bnsq[tid],  bq[tid]);
    }
}

// ------------------- BN affine params -------------------
__global__ void k_bnaff(const float* __restrict__ sum, const float* __restrict__ sq,
                        const float* __restrict__ gamma, const float* __restrict__ beta,
                        float* __restrict__ a, float* __restrict__ c,
                        int D, float invN)
{
    int j = blockIdx.x * blockDim.x + threadIdx.x;
    if (j >= D) return;
    float m   = sum[j] * invN;
    float var = sq[j] * invN - m * m;
    float aj  = gamma[j] * rsqrtf(var + 1e-5f);
    a[j] = aj;
    c[j] = beta[j] - aj * m;
}

// Wmod[k][j] = a[k] * W[k][j]
__global__ void k_wprep(const float* __restrict__ W) {
    int i = blockIdx.x * blockDim.x + threadIdx.x;
    if (i < DF * DF) g_Wmod[i] = g_affa[i >> 7] * W[i];
}
// d[j] = sum_k c[k] * W[k][j]
__global__ void k_dvec(const float* __restrict__ W) {
    int j = threadIdx.x;
    if (j < DF) {
        float s = 0.f;
        for (int k = 0; k < DF; k++) s = fmaf(g_affc[k], W[k * DF + j], s);
        g_dvec[j] = s;
    }
}

// ------------------- global_add_pool -------------------
__global__ void k_pool(const float* __restrict__ x, const int* __restrict__ batch) {
    int lane = threadIdx.x & 31;
    int w    = (blockIdx.x * blockDim.x + threadIdx.x) >> 5;
    int nW   = (gridDim.x * blockDim.x) >> 5;
    int C    = (NN + nW - 1) / nW;
    int beg = w * C;
    int end = beg + C; if (end > NN) end = NN;
    if (beg >= end) return;

    float a0 = 0, a1 = 0, a2 = 0, a3 = 0, cntf = 0;
    int cur = batch[beg];
    for (int v = beg; v < end; v++) {
        int g = batch[v];
        if (g != cur) {
            atomicAdd(&g_pool[cur * DF + lane * 4 + 0], a0);
            atomicAdd(&g_pool[cur * DF + lane * 4 + 1], a1);
            atomicAdd(&g_pool[cur * DF + lane * 4 + 2], a2);
            atomicAdd(&g_pool[cur * DF + lane * 4 + 3], a3);
            if (lane == 0) atomicAdd(&g_gcnt[cur], cntf);
            a0 = a1 = a2 = a3 = 0.f; cntf = 0.f; cur = g;
        }
        float4 xv = *((const float4*)(x + (size_t)v * DF) + lane);
        a0 += xv.x; a1 += xv.y; a2 += xv.z; a3 += xv.w; cntf += 1.f;
    }
    atomicAdd(&g_pool[cur * DF + lane * 4 + 0], a0);
    atomicAdd(&g_pool[cur * DF + lane * 4 + 1], a1);
    atomicAdd(&g_pool[cur * DF + lane * 4 + 2], a2);
    atomicAdd(&g_pool[cur * DF + lane * 4 + 3], a3);
    if (lane == 0) atomicAdd(&g_gcnt[cur], cntf);
}

// ------------------- head -------------------
__global__ void __launch_bounds__(256) k_hg0(const float* __restrict__ Wh0,
                                             const float* __restrict__ bh0) {
    __shared__ float sx[DF];
    int g = blockIdx.x, j = threadIdx.x;
    if (j < DF) sx[j] = g_affa[j] * g_pool[g * DF + j] + g_affc[j] * g_gcnt[g];
    __syncthreads();
    float acc = bh0[j];
#pragma unroll 8
    for (int k = 0; k < DF; k++) acc = fmaf(sx[k], Wh0[k * DH + j], acc);
    float v = fmaxf(acc, 0.f);
    g_h0[g * DH + j] = v;
    atomicAdd(&g_s0[j], v);
    atomicAdd(&g_q0[j], v * v);
}
__global__ void __launch_bounds__(256) k_hg1(const float* __restrict__ Wh1,
                                             const float* __restrict__ bh1) {
    __shared__ float sx[DH];
    int g = blockIdx.x, j = threadIdx.x;
    sx[j] = g_ha[j] * g_h0[g * DH + j] + g_hc[j];
    __syncthreads();
    float acc = bh1[j];
#pragma unroll 8
    for (int k = 0; k < DH; k++) acc = fmaf(sx[k], Wh1[k * DH + j], acc);
    float v = fmaxf(acc, 0.f);
    g_h1[g * DH + j] = v;
    atomicAdd(&g_s0[j], v);
    atomicAdd(&g_q0[j], v * v);
}
__global__ void __launch_bounds__(256) k_final(const float* __restrict__ Wout,
                                               const float* __restrict__ bout,
                                               float* __restrict__ out) {
    __shared__ float red[DH];
    int g = blockIdx.x, t = threadIdx.x;
    red[t] = (g_ha[t] * g_h1[g * DH + t] + g_hc[t]) * Wout[t];
    __syncthreads();
    for (int o = DH / 2; o > 0; o >>= 1) {
        if (t < o) red[t] += red[t + o];
        __syncthreads();
    }
    if (t == 0) out[g] = red[0] + bout[0];
}

// ------------------- launch -------------------
extern "C" void kernel_launch(void* const* d_in, const int* in_sizes, int n_in,
                              void* d_out, int out_size) {
    const float* x   = (const float*)d_in[0];
    const int*   ei  = (const int*)d_in[1];
    const int*   bat = (const int*)d_in[2];
    const float* Wc  = (const float*)d_in[3];
    const float* bc  = (const float*)d_in[4];
    const float* gc  = (const float*)d_in[5];
    const float* bec = (const float*)d_in[6];
    const float* Wh0 = (const float*)d_in[7];
    const float* bh0 = (const float*)d_in[8];
    const float* gh0 = (const float*)d_in[9];
    const float* beh0= (const float*)d_in[10];
    const float* Wh1 = (const float*)d_in[11];
    const float* bh1 = (const float*)d_in[12];
    const float* gh1 = (const float*)d_in[13];
    const float* beh1= (const float*)d_in[14];
    const float* Wout= (const float*)d_in[15];
    const float* bout= (const float*)d_in[16];
    float* out = (float*)d_out;

    const int* src = ei;
    const int* dst = ei + NE;

    float *p_x0, *p_x1, *p_h, *p_Wmod, *p_dvec, *p_bnsum, *p_bnsq, *p_dinv;
    float *p_affa, *p_affc, *p_pool, *p_gcnt, *p_s0, *p_q0, *p_ha, *p_hc;
    int   *p_cnt;
    cudaGetSymbolAddress((void**)&p_x0,   g_x0);
    cudaGetSymbolAddress((void**)&p_x1,   g_x1);
    cudaGetSymbolAddress((void**)&p_h,    g_h);
    cudaGetSymbolAddress((void**)&p_Wmod, g_Wmod);
    cudaGetSymbolAddress((void**)&p_dvec, g_dvec);
    cudaGetSymbolAddress((void**)&p_dinv, g_dinv);
    cudaGetSymbolAddress((void**)&p_bnsum,g_bnsum);
    cudaGetSymbolAddress((void**)&p_bnsq, g_bnsq);
    cudaGetSymbolAddress((void**)&p_affa, g_affa);
    cudaGetSymbolAddress((void**)&p_affc, g_affc);
    cudaGetSymbolAddress((void**)&p_pool, g_pool);
    cudaGetSymbolAddress((void**)&p_gcnt, g_gcnt);
    cudaGetSymbolAddress((void**)&p_s0,   g_s0);
    cudaGetSymbolAddress((void**)&p_q0,   g_q0);
    cudaGetSymbolAddress((void**)&p_ha,   g_ha);
    cudaGetSymbolAddress((void**)&p_hc,   g_hc);
    cudaGetSymbolAddress((void**)&p_cnt,  g_cnt);

    const int T = 256;
    const int gemmBlocks = (NN + 127) / 128;

    // ---- CSR build + degree ----
    k_zero_i<<<(NN + T - 1) / T, T>>>(p_cnt, NN);
    k_hist<<<(NE + T - 1) / T, T>>>(dst);
    k_dinv<<<(NN + T - 1) / T, T>>>();
    k_scanA<<<SB, 256>>>();
    k_scanB<<<1, 512>>>();
    k_scanC<<<SB, 256>>>();
    k_fill<<<(NE + T - 1) / T, T>>>(src, dst);

    // ---- conv layer 0 ----
    k_sgemm<<<gemmBlocks, T>>>(x, Wc, nullptr, p_dinv, p_h, NN);
    k_zero_f<<<1, DF>>>(p_bnsum, DF);
    k_zero_f<<<1, DF>>>(p_bnsq, DF);
    k_agg<<<2048, T>>>(p_h, bc, p_x0);
    k_bnaff<<<1, DF>>>(p_bnsum, p_bnsq, gc, bec, p_affa, p_affc, DF, 1.0f / NN);

    // ---- conv layer 1 (BN0 folded into GEMM) ----
    k_wprep<<<(DF * DF + T - 1) / T, T>>>(Wc + DF * DF);
    k_dvec<<<1, DF>>>(Wc + DF * DF);
    k_sgemm<<<gemmBlocks, T>>>(p_x0, p_Wmod, p_dvec, p_dinv, p_h, NN);
    k_zero_f<<<1, DF>>>(p_bnsum, DF);
    k_zero_f<<<1, DF>>>(p_bnsq, DF);
    k_agg<<<2048, T>>>(p_h, bc + DF, p_x1);
    k_bnaff<<<1, DF>>>(p_bnsum, p_bnsq, gc + DF, bec + DF, p_affa, p_affc, DF, 1.0f / NN);

    // ---- conv layer 2 ----
    k_wprep<<<(DF * DF + T - 1) / T, T>>>(Wc + 2 * DF * DF);
    k_dvec<<<1, DF>>>(Wc + 2 * DF * DF);
    k_sgemm<<<gemmBlocks, T>>>(p_x1, p_Wmod, p_dvec, p_dinv, p_h, NN);
    k_zero_f<<<1, DF>>>(p_bnsum, DF);
    k_zero_f<<<1, DF>>>(p_bnsq, DF);
    k_agg<<<2048, T>>>(p_h, bc + 2 * DF, p_x0);
    k_bnaff<<<1, DF>>>(p_bnsum, p_bnsq, gc + 2 * DF, bec + 2 * DF, p_affa, p_affc, DF, 1.0f / NN);

    // ---- pool (BN2 applied in head gemm0 via g_affa/g_affc) ----
    k_zero_f<<<(NG * DF + T - 1) / T, T>>>(p_pool, NG * DF);
    k_zero_f<<<(NG + T - 1) / T, T>>>(p_gcnt, NG);
    k_pool<<<128, T>>>(p_x0, bat);

    // ---- head ----
    k_zero_f<<<1, DH>>>(p_s0, DH);
    k_zero_f<<<1, DH>>>(p_q0, DH);
    k_hg0<<<NG, DH>>>(Wh0, bh0);
    k_bnaff<<<1, DH>>>(p_s0, p_q0, gh0, beh0, p_ha, p_hc, DH, 1.0f / NG);
    k_zero_f<<<1, DH>>>(p_s0, DH);
    k_zero_f<<<1, DH>>>(p_q0, DH);
    k_hg1<<<NG, DH>>>(Wh1, bh1);
    k_bnaff<<<1, DH>>>(p_s0, p_q0, gh1, beh1, p_ha, p_hc, DH, 1.0f / NG);
    k_final<<<NG, DH>>>(Wout, bout, out);
}

// round 6
// speedup vs baseline: 1.3810x; 1.2799x over previous
#include <cuda_runtime.h>
#include <math.h>

#define NN 100000
#define NE 1600000
#define DF 128
#define NG 512
#define DH 256
#define SB ((NN + 255) / 256)   // 391 scan blocks

// ------------------- scratch (__device__ globals; no allocation) -------------------
static __device__ int   g_cnt[NN];
static __device__ int   g_wptr[NN];
static __device__ int   g_rowptr[NN + 1];
static __device__ int   g_bsum[512];
static __device__ int   g_boff[512];
static __device__ int   g_col[NE];
static __device__ float g_dinv[NN];
static __device__ __align__(16) float g_x0[(size_t)NN * DF];
static __device__ __align__(16) float g_x1[(size_t)NN * DF];
static __device__ __align__(16) float g_h [(size_t)NN * DF];
static __device__ __align__(16) float g_Wmod[DF * DF];
static __device__ __align__(16) float g_dvec[DF];
static __device__ float g_bnsum[3 * DF];   // per-layer BN stats
static __device__ float g_bnsq [3 * DF];
static __device__ float g_affa[DF];
static __device__ float g_affc[DF];
static __device__ __align__(16) float g_pool[NG * DF];
static __device__ float g_gcnt[NG];
static __device__ float g_h0[NG * DH];
static __device__ float g_h1[NG * DH];
static __device__ float g_sq[4 * DH];      // s0,q0,s1,q1
static __device__ float g_ha[DH];
static __device__ float g_hc[DH];

// ------------------- one-shot init: zero every accumulator (runs each replay) ------
#define INIT_TOT (NN + 3 * DF * 2 + NG * DF + NG + 4 * DH)
__global__ void k_init() {
    int i = blockIdx.x * blockDim.x + threadIdx.x;
    if (i < NN) { g_cnt[i] = 0; return; }
    i -= NN;
    if (i < 3 * DF) { g_bnsum[i] = 0.f; return; }
    i -= 3 * DF;
    if (i < 3 * DF) { g_bnsq[i] = 0.f; return; }
    i -= 3 * DF;
    if (i < NG * DF) { g_pool[i] = 0.f; return; }
    i -= NG * DF;
    if (i < NG) { g_gcnt[i] = 0.f; return; }
    i -= NG;
    if (i < 4 * DH) g_sq[i] = 0.f;
}

// ------------------- CSR build -------------------
__global__ void k_hist(const int* __restrict__ dst) {
    int e = blockIdx.x * blockDim.x + threadIdx.x;
    if (e < NE) atomicAdd(&g_cnt[dst[e]], 1);
}
__global__ void k_dinv() {
    int v = blockIdx.x * blockDim.x + threadIdx.x;
    if (v < NN) g_dinv[v] = rsqrtf((float)g_cnt[v] + 1.0f);
}
__global__ void __launch_bounds__(256) k_scanA() {
    __shared__ int s[256];
    int t = threadIdx.x;
    int i = blockIdx.x * 256 + t;
    int v = (i < NN) ? g_cnt[i] : 0;
    s[t] = v;
    __syncthreads();
#pragma unroll
    for (int off = 1; off < 256; off <<= 1) {
        int u = (t >= off) ? s[t - off] : 0;
        __syncthreads();
        s[t] += u;
        __syncthreads();
    }
    if (i < NN) g_rowptr[i] = s[t] - v;
    if (t == 255) g_bsum[blockIdx.x] = s[255];
}
__global__ void __launch_bounds__(512) k_scanB() {
    __shared__ int s[512];
    int t = threadIdx.x;
    int v = (t < SB) ? g_bsum[t] : 0;
    s[t] = v;
    __syncthreads();
#pragma unroll
    for (int off = 1; off < 512; off <<= 1) {
        int u = (t >= off) ? s[t - off] : 0;
        __syncthreads();
        s[t] += u;
        __syncthreads();
    }
    g_boff[t] = s[t] - v;
    if (t == 0) g_rowptr[NN] = NE;
}
__global__ void __launch_bounds__(256) k_scanC() {
    int i = blockIdx.x * 256 + threadIdx.x;
    if (i < NN) {
        int r = g_rowptr[i] + g_boff[blockIdx.x];
        g_rowptr[i] = r;
        g_wptr[i]   = r;
    }
}
__global__ void k_fill(const int* __restrict__ src, const int* __restrict__ dst) {
    int e = blockIdx.x * blockDim.x + threadIdx.x;
    if (e < NE) {
        int v = dst[e];
        int pos = atomicAdd(&g_wptr[v], 1);
        g_col[pos] = src[e];
    }
}

// ------------------- SGEMM: C[M,128] = A[M,128] @ B[128,128] (+ dvec row) -----------
// BM=128, BN=128, BK=8, 128 threads, TM=16, TN=8
__global__ void __launch_bounds__(128) k_sgemm(
    const float* __restrict__ A, const float* __restrict__ B,
    const float* __restrict__ dvec, float* __restrict__ C, int M)
{
    const int BM = 128, BN = 128, BK = 8, TM = 16, TN = 8;
    __shared__ __align__(16) float As[BK * BM];  // transposed: As[k][m]
    __shared__ __align__(16) float Bs[BK * BN];

    int tid  = threadIdx.x;
    int row0 = blockIdx.x * BM;
    int tr = tid >> 4;            // 0..7  -> rows tr*16..+15
    int tc = tid & 15;            // 0..15 -> cols tc*8..+7

    float acc[TM][TN];
#pragma unroll
    for (int i = 0; i < TM; i++)
#pragma unroll
        for (int j = 0; j < TN; j++) acc[i][j] = 0.f;

    int arow = tid;               // 0..127
    int brow = tid >> 4;          // 0..7
    int bcol = (tid & 15) * 8;    // 0..120

    for (int kk = 0; kk < 128; kk += BK) {
        float4 a0, a1;
        if (row0 + arow < M) {
            a0 = *(const float4*)(A + (size_t)(row0 + arow) * 128 + kk);
            a1 = *(const float4*)(A + (size_t)(row0 + arow) * 128 + kk + 4);
        } else {
            a0 = make_float4(0.f, 0.f, 0.f, 0.f);
            a1 = a0;
        }
        As[0 * BM + arow] = a0.x; As[1 * BM + arow] = a0.y;
        As[2 * BM + arow] = a0.z; As[3 * BM + arow] = a0.w;
        As[4 * BM + arow] = a1.x; As[5 * BM + arow] = a1.y;
        As[6 * BM + arow] = a1.z; As[7 * BM + arow] = a1.w;

        float4 b0 = *(const float4*)(B + (size_t)(kk + brow) * 128 + bcol);
        float4 b1 = *(const float4*)(B + (size_t)(kk + brow) * 128 + bcol + 4);
        *(float4*)(Bs + brow * BN + bcol)     = b0;
        *(float4*)(Bs + brow * BN + bcol + 4) = b1;
        __syncthreads();

#pragma unroll
        for (int k = 0; k < BK; k++) {
            float ra[TM], rb[TN];
#pragma unroll
            for (int p = 0; p < 4; p++) {
                float4 r = *(const float4*)(As + k * BM + tr * TM + p * 4);
                ra[p * 4 + 0] = r.x; ra[p * 4 + 1] = r.y;
                ra[p * 4 + 2] = r.z; ra[p * 4 + 3] = r.w;
            }
            float4 rb0 = *(const float4*)(Bs + k * BN + tc * TN);
            float4 rb1 = *(const float4*)(Bs + k * BN + tc * TN + 4);
            rb[0] = rb0.x; rb[1] = rb0.y; rb[2] = rb0.z; rb[3] = rb0.w;
            rb[4] = rb1.x; rb[5] = rb1.y; rb[6] = rb1.z; rb[7] = rb1.w;
#pragma unroll
            for (int i = 0; i < TM; i++)
#pragma unroll
                for (int j = 0; j < TN; j++)
                    acc[i][j] = fmaf(ra[i], rb[j], acc[i][j]);
        }
        __syncthreads();
    }

    float dv[TN];
#pragma unroll
    for (int j = 0; j < TN; j++) dv[j] = dvec ? dvec[tc * TN + j] : 0.f;

#pragma unroll
    for (int i = 0; i < TM; i++) {
        int r = row0 + tr * TM + i;
        if (r < M) {
            float4 o0 = make_float4(acc[i][0] + dv[0], acc[i][1] + dv[1],
                                    acc[i][2] + dv[2], acc[i][3] + dv[3]);
            float4 o1 = make_float4(acc[i][4] + dv[4], acc[i][5] + dv[5],
                                    acc[i][6] + dv[6], acc[i][7] + dv[7]);
            *(float4*)(C + (size_t)r * 128 + tc * TN)     = o0;
            *(float4*)(C + (size_t)r * 128 + tc * TN + 4) = o1;
        }
    }
}

// ------------------- GCN aggregation + bias + relu + fused BN stats (R2 structure) --
__global__ void __launch_bounds__(256) k_agg(
    const float* __restrict__ h, const float* __restrict__ bias,
    float* __restrict__ xout, float* __restrict__ bnsum, float* __restrict__ bnsq)
{
    __shared__ float bs[DF], bq[DF];
    int tid = threadIdx.x;
    if (tid < DF) { bs[tid] = 0.f; bq[tid] = 0.f; }
    __syncthreads();

    int lane = tid & 31;
    int w    = tid >> 5;
    int warpId = blockIdx.x * (blockDim.x >> 5) + w;
    int nW     = gridDim.x * (blockDim.x >> 5);

    float4 bv = *(const float4*)(bias + lane * 4);
    float ls0 = 0, ls1 = 0, ls2 = 0, ls3 = 0;
    float lq0 = 0, lq1 = 0, lq2 = 0, lq3 = 0;

    for (int v = warpId; v < NN; v += nW) {
        float dv = g_dinv[v];
        float4 hv = *((const float4*)(h + (size_t)v * DF) + lane);  // self loop
        float ax = hv.x * dv, ay = hv.y * dv, az = hv.z * dv, aw = hv.w * dv;

        int beg = g_rowptr[v], end = g_rowptr[v + 1];
        for (int e0 = beg; e0 < end; e0 += 32) {
            int idx = e0 + lane;
            int   sl = (idx < end) ? g_col[idx]  : 0;
            float dl = (idx < end) ? g_dinv[sl]  : 0.f;
            int m = end - e0; if (m > 32) m = 32;
            for (int j = 0; j < m; j++) {
                int   sj  = __shfl_sync(0xffffffffu, sl, j);
                float dsj = __shfl_sync(0xffffffffu, dl, j);
                float4 hs = *((const float4*)(h + (size_t)sj * DF) + lane);
                ax = fmaf(hs.x, dsj, ax);
                ay = fmaf(hs.y, dsj, ay);
                az = fmaf(hs.z, dsj, az);
                aw = fmaf(hs.w, dsj, aw);
            }
        }
        float ox = fmaxf(fmaf(ax, dv, bv.x), 0.f);
        float oy = fmaxf(fmaf(ay, dv, bv.y), 0.f);
        float oz = fmaxf(fmaf(az, dv, bv.z), 0.f);
        float ow = fmaxf(fmaf(aw, dv, bv.w), 0.f);
        *((float4*)(xout + (size_t)v * DF) + lane) = make_float4(ox, oy, oz, ow);
        ls0 += ox; lq0 += ox * ox;
        ls1 += oy; lq1 += oy * oy;
        ls2 += oz; lq2 += oz * oz;
        ls3 += ow; lq3 += ow * ow;
    }
    atomicAdd(&bs[lane * 4 + 0], ls0); atomicAdd(&bq[lane * 4 + 0], lq0);
    atomicAdd(&bs[lane * 4 + 1], ls1); atomicAdd(&bq[lane * 4 + 1], lq1);
    atomicAdd(&bs[lane * 4 + 2], ls2); atomicAdd(&bq[lane * 4 + 2], lq2);
    atomicAdd(&bs[lane * 4 + 3], ls3); atomicAdd(&bq[lane * 4 + 3], lq3);
    __syncthreads();
    if (tid < DF) {
        atomicAdd(&bnsum[tid], bs[tid]);
        atomicAdd(&bnsq[tid],  bq[tid]);
    }
}

// ------------------- BN affine params -------------------
__global__ void k_bnaff(const float* __restrict__ sum, const float* __restrict__ sq,
                        const float* __restrict__ gamma, const float* __restrict__ beta,
                        float* __restrict__ a, float* __restrict__ c,
                        int D, float invN)
{
    int j = blockIdx.x * blockDim.x + threadIdx.x;
    if (j >= D) return;
    float m   = sum[j] * invN;
    float var = sq[j] * invN - m * m;
    float aj  = gamma[j] * rsqrtf(var + 1e-5f);
    a[j] = aj;
    c[j] = beta[j] - aj * m;
}

// Wmod[k][j] = a[k]*W[k][j]  (blocks 0..63) ; block 64: dvec[j] = sum_k c[k]*W[k][j]
__global__ void k_wprep(const float* __restrict__ W) {
    if (blockIdx.x < 64) {
        int i = blockIdx.x * 256 + threadIdx.x;
        g_Wmod[i] = g_affa[i >> 7] * W[i];
    } else {
        int j = threadIdx.x;
        if (j < DF) {
            float s = 0.f;
#pragma unroll 8
            for (int k = 0; k < DF; k++) s = fmaf(g_affc[k], W[k * DF + j], s);
            g_dvec[j] = s;
        }
    }
}

// ------------------- global_add_pool (batch sorted -> run-length) -------------------
__global__ void k_pool(const float* __restrict__ x, const int* __restrict__ batch) {
    int lane = threadIdx.x & 31;
    int w    = (blockIdx.x * blockDim.x + threadIdx.x) >> 5;
    int nW   = (gridDim.x * blockDim.x) >> 5;
    int C    = (NN + nW - 1) / nW;
    int beg = w * C;
    int end = beg + C; if (end > NN) end = NN;
    if (beg >= end) return;

    float a0 = 0, a1 = 0, a2 = 0, a3 = 0, cntf = 0;
    int cur = batch[beg];
    for (int v = beg; v < end; v++) {
        int g = batch[v];
        if (g != cur) {
            atomicAdd(&g_pool[cur * DF + lane * 4 + 0], a0);
            atomicAdd(&g_pool[cur * DF + lane * 4 + 1], a1);
            atomicAdd(&g_pool[cur * DF + lane * 4 + 2], a2);
            atomicAdd(&g_pool[cur * DF + lane * 4 + 3], a3);
            if (lane == 0) atomicAdd(&g_gcnt[cur], cntf);
            a0 = a1 = a2 = a3 = 0.f; cntf = 0.f; cur = g;
        }
        float4 xv = *((const float4*)(x + (size_t)v * DF) + lane);
        a0 += xv.x; a1 += xv.y; a2 += xv.z; a3 += xv.w; cntf += 1.f;
    }
    atomicAdd(&g_pool[cur * DF + lane * 4 + 0], a0);
    atomicAdd(&g_pool[cur * DF + lane * 4 + 1], a1);
    atomicAdd(&g_pool[cur * DF + lane * 4 + 2], a2);
    atomicAdd(&g_pool[cur * DF + lane * 4 + 3], a3);
    if (lane == 0) atomicAdd(&g_gcnt[cur], cntf);
}

// ------------------- head -------------------
__global__ void __launch_bounds__(256) k_hg0(const float* __restrict__ Wh0,
                                             const float* __restrict__ bh0) {
    __shared__ float sx[DF];
    int g = blockIdx.x, j = threadIdx.x;
    if (j < DF) sx[j] = g_affa[j] * g_pool[g * DF + j] + g_affc[j] * g_gcnt[g];
    __syncthreads();
    float acc = bh0[j];
#pragma unroll 8
    for (int k = 0; k < DF; k++) acc = fmaf(sx[k], Wh0[k * DH + j], acc);
    float v = fmaxf(acc, 0.f);
    g_h0[g * DH + j] = v;
    atomicAdd(&g_sq[j], v);
    atomicAdd(&g_sq[DH + j], v * v);
}
__global__ void __launch_bounds__(256) k_hg1(const float* __restrict__ Wh1,
                                             const float* __restrict__ bh1) {
    __shared__ float sx[DH];
    int g = blockIdx.x, j = threadIdx.x;
    sx[j] = g_ha[j] * g_h0[g * DH + j] + g_hc[j];
    __syncthreads();
    float acc = bh1[j];
#pragma unroll 8
    for (int k = 0; k < DH; k++) acc = fmaf(sx[k], Wh1[k * DH + j], acc);
    float v = fmaxf(acc, 0.f);
    g_h1[g * DH + j] = v;
    atomicAdd(&g_sq[2 * DH + j], v);
    atomicAdd(&g_sq[3 * DH + j], v * v);
}
__global__ void __launch_bounds__(256) k_final(const float* __restrict__ Wout,
                                               const float* __restrict__ bout,
                                               float* __restrict__ out) {
    __shared__ float red[DH];
    int g = blockIdx.x, t = threadIdx.x;
    red[t] = (g_ha[t] * g_h1[g * DH + t] + g_hc[t]) * Wout[t];
    __syncthreads();
    for (int o = DH / 2; o > 0; o >>= 1) {
        if (t < o) red[t] += red[t + o];
        __syncthreads();
    }
    if (t == 0) out[g] = red[0] + bout[0];
}

// ------------------- launch -------------------
extern "C" void kernel_launch(void* const* d_in, const int* in_sizes, int n_in,
                              void* d_out, int out_size) {
    const float* x   = (const float*)d_in[0];
    const int*   ei  = (const int*)d_in[1];
    const int*   bat = (const int*)d_in[2];
    const float* Wc  = (const float*)d_in[3];
    const float* bc  = (const float*)d_in[4];
    const float* gc  = (const float*)d_in[5];
    const float* bec = (const float*)d_in[6];
    const float* Wh0 = (const float*)d_in[7];
    const float* bh0 = (const float*)d_in[8];
    const float* gh0 = (const float*)d_in[9];
    const float* beh0= (const float*)d_in[10];
    const float* Wh1 = (const float*)d_in[11];
    const float* bh1 = (const float*)d_in[12];
    const float* gh1 = (const float*)d_in[13];
    const float* beh1= (const float*)d_in[14];
    const float* Wout= (const float*)d_in[15];
    const float* bout= (const float*)d_in[16];
    float* out = (float*)d_out;

    const int* src = ei;
    const int* dst = ei + NE;

    float *p_x0, *p_x1, *p_h, *p_Wmod, *p_dvec, *p_bnsum, *p_bnsq;
    float *p_affa, *p_affc, *p_sq, *p_ha, *p_hc;
    cudaGetSymbolAddress((void**)&p_x0,   g_x0);
    cudaGetSymbolAddress((void**)&p_x1,   g_x1);
    cudaGetSymbolAddress((void**)&p_h,    g_h);
    cudaGetSymbolAddress((void**)&p_Wmod, g_Wmod);
    cudaGetSymbolAddress((void**)&p_dvec, g_dvec);
    cudaGetSymbolAddress((void**)&p_bnsum,g_bnsum);
    cudaGetSymbolAddress((void**)&p_bnsq, g_bnsq);
    cudaGetSymbolAddress((void**)&p_affa, g_affa);
    cudaGetSymbolAddress((void**)&p_affc, g_affc);
    cudaGetSymbolAddress((void**)&p_sq,   g_sq);
    cudaGetSymbolAddress((void**)&p_ha,   g_ha);
    cudaGetSymbolAddress((void**)&p_hc,   g_hc);

    const int T = 256;
    const int gemmBlocks = (NN + 127) / 128;

    // ---- init + CSR build + degree ----
    k_init<<<(INIT_TOT + T - 1) / T, T>>>();
    k_hist<<<(NE + T - 1) / T, T>>>(dst);
    k_dinv<<<(NN + T - 1) / T, T>>>();
    k_scanA<<<SB, 256>>>();
    k_scanB<<<1, 512>>>();
    k_scanC<<<SB, 256>>>();
    k_fill<<<(NE + T - 1) / T, T>>>(src, dst);

    // ---- conv layer 0 ----
    k_sgemm<<<gemmBlocks, 128>>>(x, Wc, nullptr, p_h, NN);
    k_agg<<<2048, T>>>(p_h, bc, p_x0, p_bnsum, p_bnsq);
    k_bnaff<<<1, DF>>>(p_bnsum, p_bnsq, gc, bec, p_affa, p_affc, DF, 1.0f / NN);

    // ---- conv layer 1 (BN0 folded into GEMM) ----
    k_wprep<<<65, T>>>(Wc + DF * DF);
    k_sgemm<<<gemmBlocks, 128>>>(p_x0, p_Wmod, p_dvec, p_h, NN);
    k_agg<<<2048, T>>>(p_h, bc + DF, p_x1, p_bnsum + DF, p_bnsq + DF);
    k_bnaff<<<1, DF>>>(p_bnsum + DF, p_bnsq + DF, gc + DF, bec + DF, p_affa, p_affc, DF, 1.0f / NN);

    // ---- conv layer 2 ----
    k_wprep<<<65, T>>>(Wc + 2 * DF * DF);
    k_sgemm<<<gemmBlocks, 128>>>(p_x1, p_Wmod, p_dvec, p_h, NN);
    k_agg<<<2048, T>>>(p_h, bc + 2 * DF, p_x0, p_bnsum + 2 * DF, p_bnsq + 2 * DF);
    k_bnaff<<<1, DF>>>(p_bnsum + 2 * DF, p_bnsq + 2 * DF, gc + 2 * DF, bec + 2 * DF, p_affa, p_affc, DF, 1.0f / NN);

    // ---- pool (BN2 applied in head gemm0 via g_affa/g_affc) ----
    k_pool<<<128, T>>>(p_x0, bat);

    // ---- head ----
    k_hg0<<<NG, DH>>>(Wh0, bh0);
    k_bnaff<<<1, DH>>>(p_sq, p_sq + DH, gh0, beh0, p_ha, p_hc, DH, 1.0f / NG);
    k_hg1<<<NG, DH>>>(Wh1, bh1);
    k_bnaff<<<1, DH>>>(p_sq + 2 * DH, p_sq + 3 * DH, gh1, beh1, p_ha, p_hc, DH, 1.0f / NG);
    k_final<<<NG, DH>>>(Wout, bout, out);
}

// round 7
// speedup vs baseline: 1.5026x; 1.0881x over previous
#include <cuda_runtime.h>
#include <math.h>

#define NN 100000
#define NE 1600000
#define DF 128
#define NG 512
#define DH 256
#define SB ((NN + 255) / 256)   // 391 scan blocks

// ------------------- scratch (__device__ globals; no allocation) -------------------
static __device__ int   g_cnt[NN];
static __device__ int   g_wptr[NN];
static __device__ int   g_rowptr[NN + 1];
static __device__ int   g_bsum[512];
static __device__ int   g_boff[512];
static __device__ int   g_col[NE];
static __device__ float g_dinv[NN];
static __device__ __align__(16) float g_x0[(size_t)NN * DF];
static __device__ __align__(16) float g_x1[(size_t)NN * DF];
static __device__ __align__(16) float g_h [(size_t)NN * DF];
static __device__ __align__(16) float g_Wmod[DF * DF];
static __device__ __align__(16) float g_dvec[DF];
static __device__ float g_bnsum[3 * DF];   // per-layer BN stats
static __device__ float g_bnsq [3 * DF];
static __device__ float g_affa[DF];
static __device__ float g_affc[DF];
static __device__ __align__(16) float g_pool[NG * DF];
static __device__ float g_gcnt[NG];
static __device__ float g_h0[NG * DH];
static __device__ float g_h1[NG * DH];
static __device__ float g_sq[4 * DH];      // s0,q0,s1,q1
static __device__ float g_ha[DH];
static __device__ float g_hc[DH];

// ------------------- one-shot init: zero every accumulator (runs each replay) ------
#define INIT_TOT (NN + 3 * DF * 2 + NG * DF + NG + 4 * DH)
__global__ void k_init() {
    int i = blockIdx.x * blockDim.x + threadIdx.x;
    if (i < NN) { g_cnt[i] = 0; return; }
    i -= NN;
    if (i < 3 * DF) { g_bnsum[i] = 0.f; return; }
    i -= 3 * DF;
    if (i < 3 * DF) { g_bnsq[i] = 0.f; return; }
    i -= 3 * DF;
    if (i < NG * DF) { g_pool[i] = 0.f; return; }
    i -= NG * DF;
    if (i < NG) { g_gcnt[i] = 0.f; return; }
    i -= NG;
    if (i < 4 * DH) g_sq[i] = 0.f;
}

// ------------------- CSR build -------------------
__global__ void k_hist(const int* __restrict__ dst) {
    int e = blockIdx.x * blockDim.x + threadIdx.x;
    if (e < NE) atomicAdd(&g_cnt[dst[e]], 1);
}
__global__ void k_dinv() {
    int v = blockIdx.x * blockDim.x + threadIdx.x;
    if (v < NN) g_dinv[v] = rsqrtf((float)g_cnt[v] + 1.0f);
}
__global__ void __launch_bounds__(256) k_scanA() {
    __shared__ int s[256];
    int t = threadIdx.x;
    int i = blockIdx.x * 256 + t;
    int v = (i < NN) ? g_cnt[i] : 0;
    s[t] = v;
    __syncthreads();
#pragma unroll
    for (int off = 1; off < 256; off <<= 1) {
        int u = (t >= off) ? s[t - off] : 0;
        __syncthreads();
        s[t] += u;
        __syncthreads();
    }
    if (i < NN) g_rowptr[i] = s[t] - v;
    if (t == 255) g_bsum[blockIdx.x] = s[255];
}
__global__ void __launch_bounds__(512) k_scanB() {
    __shared__ int s[512];
    int t = threadIdx.x;
    int v = (t < SB) ? g_bsum[t] : 0;
    s[t] = v;
    __syncthreads();
#pragma unroll
    for (int off = 1; off < 512; off <<= 1) {
        int u = (t >= off) ? s[t - off] : 0;
        __syncthreads();
        s[t] += u;
        __syncthreads();
    }
    g_boff[t] = s[t] - v;
    if (t == 0) g_rowptr[NN] = NE;
}
__global__ void __launch_bounds__(256) k_scanC() {
    int i = blockIdx.x * 256 + threadIdx.x;
    if (i < NN) {
        int r = g_rowptr[i] + g_boff[blockIdx.x];
        g_rowptr[i] = r;
        g_wptr[i]   = r;
    }
}
__global__ void k_fill(const int* __restrict__ src, const int* __restrict__ dst) {
    int e = blockIdx.x * blockDim.x + threadIdx.x;
    if (e < NE) {
        int v = dst[e];
        int pos = atomicAdd(&g_wptr[v], 1);
        g_col[pos] = src[e];
    }
}

// ------------------- SGEMM: C[M,128] = A[M,128] @ B[128,128] (+ dvec row) -----------
// BM=128, BN=128, BK=8, TM=8, TN=8, 256 threads (exact R2 version)
__global__ void __launch_bounds__(256) k_sgemm(
    const float* __restrict__ A, const float* __restrict__ B,
    const float* __restrict__ dvec, float* __restrict__ C, int M)
{
    const int BM = 128, BN = 128, BK = 8, TM = 8, TN = 8;
    __shared__ __align__(16) float As[BK * BM];  // transposed: As[k][m]
    __shared__ __align__(16) float Bs[BK * BN];

    int tid  = threadIdx.x;
    int row0 = blockIdx.x * BM;
    int tr = tid / 16;            // 0..15
    int tc = tid % 16;            // 0..15

    float acc[TM][TN];
#pragma unroll
    for (int i = 0; i < TM; i++)
#pragma unroll
        for (int j = 0; j < TN; j++) acc[i][j] = 0.f;

    int arow = tid >> 1;           // 0..127
    int acol = (tid & 1) * 4;      // 0 or 4
    int brow = tid >> 5;           // 0..7
    int bcol = (tid & 31) * 4;     // 0..124

    for (int kk = 0; kk < 128; kk += BK) {
        float4 av;
        if (row0 + arow < M)
            av = *(const float4*)(A + (size_t)(row0 + arow) * 128 + kk + acol);
        else
            av = make_float4(0.f, 0.f, 0.f, 0.f);
        As[(acol + 0) * BM + arow] = av.x;
        As[(acol + 1) * BM + arow] = av.y;
        As[(acol + 2) * BM + arow] = av.z;
        As[(acol + 3) * BM + arow] = av.w;

        float4 bv = *(const float4*)(B + (size_t)(kk + brow) * 128 + bcol);
        *(float4*)(Bs + brow * BN + bcol) = bv;
        __syncthreads();

#pragma unroll
        for (int k = 0; k < BK; k++) {
            float ra[TM], rb[TN];
            float4 ra0 = *(const float4*)(As + k * BM + tr * TM);
            float4 ra1 = *(const float4*)(As + k * BM + tr * TM + 4);
            ra[0] = ra0.x; ra[1] = ra0.y; ra[2] = ra0.z; ra[3] = ra0.w;
            ra[4] = ra1.x; ra[5] = ra1.y; ra[6] = ra1.z; ra[7] = ra1.w;
            float4 rb0 = *(const float4*)(Bs + k * BN + tc * TN);
            float4 rb1 = *(const float4*)(Bs + k * BN + tc * TN + 4);
            rb[0] = rb0.x; rb[1] = rb0.y; rb[2] = rb0.z; rb[3] = rb0.w;
            rb[4] = rb1.x; rb[5] = rb1.y; rb[6] = rb1.z; rb[7] = rb1.w;
#pragma unroll
            for (int i = 0; i < TM; i++)
#pragma unroll
                for (int j = 0; j < TN; j++)
                    acc[i][j] = fmaf(ra[i], rb[j], acc[i][j]);
        }
        __syncthreads();
    }

    float dv[TN];
#pragma unroll
    for (int j = 0; j < TN; j++) dv[j] = dvec ? dvec[tc * TN + j] : 0.f;

#pragma unroll
    for (int i = 0; i < TM; i++) {
        int r = row0 + tr * TM + i;
        if (r < M) {
            float4 o0 = make_float4(acc[i][0] + dv[0], acc[i][1] + dv[1],
                                    acc[i][2] + dv[2], acc[i][3] + dv[3]);
            float4 o1 = make_float4(acc[i][4] + dv[4], acc[i][5] + dv[5],
                                    acc[i][6] + dv[6], acc[i][7] + dv[7]);
            *(float4*)(C + (size_t)r * 128 + tc * TN)     = o0;
            *(float4*)(C + (size_t)r * 128 + tc * TN + 4) = o1;
        }
    }
}

// ------------------- GCN aggregation + bias + relu + fused BN stats (R2 structure) --
__global__ void __launch_bounds__(256) k_agg(
    const float* __restrict__ h, const float* __restrict__ bias,
    float* __restrict__ xout, float* __restrict__ bnsum, float* __restrict__ bnsq)
{
    __shared__ float bs[DF], bq[DF];
    int tid = threadIdx.x;
    if (tid < DF) { bs[tid] = 0.f; bq[tid] = 0.f; }
    __syncthreads();

    int lane = tid & 31;
    int w    = tid >> 5;
    int warpId = blockIdx.x * (blockDim.x >> 5) + w;
    int nW     = gridDim.x * (blockDim.x >> 5);

    float4 bv = *(const float4*)(bias + lane * 4);
    float ls0 = 0, ls1 = 0, ls2 = 0, ls3 = 0;
    float lq0 = 0, lq1 = 0, lq2 = 0, lq3 = 0;

    for (int v = warpId; v < NN; v += nW) {
        float dv = g_dinv[v];
        float4 hv = *((const float4*)(h + (size_t)v * DF) + lane);  // self loop
        float ax = hv.x * dv, ay = hv.y * dv, az = hv.z * dv, aw = hv.w * dv;

        int beg = g_rowptr[v], end = g_rowptr[v + 1];
        for (int e0 = beg; e0 < end; e0 += 32) {
            int idx = e0 + lane;
            int   sl = (idx < end) ? g_col[idx]  : 0;
            float dl = (idx < end) ? g_dinv[sl]  : 0.f;
            int m = end - e0; if (m > 32) m = 32;
            for (int j = 0; j < m; j++) {
                int   sj  = __shfl_sync(0xffffffffu, sl, j);
                float dsj = __shfl_sync(0xffffffffu, dl, j);
                float4 hs = *((const float4*)(h + (size_t)sj * DF) + lane);
                ax = fmaf(hs.x, dsj, ax);
                ay = fmaf(hs.y, dsj, ay);
                az = fmaf(hs.z, dsj, az);
                aw = fmaf(hs.w, dsj, aw);
            }
        }
        float ox = fmaxf(fmaf(ax, dv, bv.x), 0.f);
        float oy = fmaxf(fmaf(ay, dv, bv.y), 0.f);
        float oz = fmaxf(fmaf(az, dv, bv.z), 0.f);
        float ow = fmaxf(fmaf(aw, dv, bv.w), 0.f);
        *((float4*)(xout + (size_t)v * DF) + lane) = make_float4(ox, oy, oz, ow);
        ls0 += ox; lq0 += ox * ox;
        ls1 += oy; lq1 += oy * oy;
        ls2 += oz; lq2 += oz * oz;
        ls3 += ow; lq3 += ow * ow;
    }
    atomicAdd(&bs[lane * 4 + 0], ls0); atomicAdd(&bq[lane * 4 + 0], lq0);
    atomicAdd(&bs[lane * 4 + 1], ls1); atomicAdd(&bq[lane * 4 + 1], lq1);
    atomicAdd(&bs[lane * 4 + 2], ls2); atomicAdd(&bq[lane * 4 + 2], lq2);
    atomicAdd(&bs[lane * 4 + 3], ls3); atomicAdd(&bq[lane * 4 + 3], lq3);
    __syncthreads();
    if (tid < DF) {
        atomicAdd(&bnsum[tid], bs[tid]);
        atomicAdd(&bnsq[tid],  bq[tid]);
    }
}

// ------------------- BN affine params -------------------
__global__ void k_bnaff(const float* __restrict__ sum, const float* __restrict__ sq,
                        const float* __restrict__ gamma, const float* __restrict__ beta,
                        float* __restrict__ a, float* __restrict__ c,
                        int D, float invN)
{
    int j = blockIdx.x * blockDim.x + threadIdx.x;
    if (j >= D) return;
    float m   = sum[j] * invN;
    float var = sq[j] * invN - m * m;
    float aj  = gamma[j] * rsqrtf(var + 1e-5f);
    a[j] = aj;
    c[j] = beta[j] - aj * m;
}

// Wmod[k][j] = a[k]*W[k][j]  (blocks 0..63) ; block 64: dvec[j] = sum_k c[k]*W[k][j]
__global__ void k_wprep(const float* __restrict__ W) {
    if (blockIdx.x < 64) {
        int i = blockIdx.x * 256 + threadIdx.x;
        g_Wmod[i] = g_affa[i >> 7] * W[i];
    } else {
        int j = threadIdx.x;
        if (j < DF) {
            float s = 0.f;
#pragma unroll 8
            for (int k = 0; k < DF; k++) s = fmaf(g_affc[k], W[k * DF + j], s);
            g_dvec[j] = s;
        }
    }
}

// ------------------- global_add_pool (batch sorted -> run-length) -------------------
__global__ void k_pool(const float* __restrict__ x, const int* __restrict__ batch) {
    int lane = threadIdx.x & 31;
    int w    = (blockIdx.x * blockDim.x + threadIdx.x) >> 5;
    int nW   = (gridDim.x * blockDim.x) >> 5;
    int C    = (NN + nW - 1) / nW;
    int beg = w * C;
    int end = beg + C; if (end > NN) end = NN;
    if (beg >= end) return;

    float a0 = 0, a1 = 0, a2 = 0, a3 = 0, cntf = 0;
    int cur = batch[beg];
    for (int v = beg; v < end; v++) {
        int g = batch[v];
        if (g != cur) {
            atomicAdd(&g_pool[cur * DF + lane * 4 + 0], a0);
            atomicAdd(&g_pool[cur * DF + lane * 4 + 1], a1);
            atomicAdd(&g_pool[cur * DF + lane * 4 + 2], a2);
            atomicAdd(&g_pool[cur * DF + lane * 4 + 3], a3);
            if (lane == 0) atomicAdd(&g_gcnt[cur], cntf);
            a0 = a1 = a2 = a3 = 0.f; cntf = 0.f; cur = g;
        }
        float4 xv = *((const float4*)(x + (size_t)v * DF) + lane);
        a0 += xv.x; a1 += xv.y; a2 += xv.z; a3 += xv.w; cntf += 1.f;
    }
    atomicAdd(&g_pool[cur * DF + lane * 4 + 0], a0);
    atomicAdd(&g_pool[cur * DF + lane * 4 + 1], a1);
    atomicAdd(&g_pool[cur * DF + lane * 4 + 2], a2);
    atomicAdd(&g_pool[cur * DF + lane * 4 + 3], a3);
    if (lane == 0) atomicAdd(&g_gcnt[cur], cntf);
}

// ------------------- head -------------------
__global__ void __launch_bounds__(256) k_hg0(const float* __restrict__ Wh0,
                                             const float* __restrict__ bh0) {
    __shared__ float sx[DF];
    int g = blockIdx.x, j = threadIdx.x;
    if (j < DF) sx[j] = g_affa[j] * g_pool[g * DF + j] + g_affc[j] * g_gcnt[g];
    __syncthreads();
    float acc = bh0[j];
#pragma unroll 8
    for (int k = 0; k < DF; k++) acc = fmaf(sx[k], Wh0[k * DH + j], acc);
    float v = fmaxf(acc, 0.f);
    g_h0[g * DH + j] = v;
    atomicAdd(&g_sq[j], v);
    atomicAdd(&g_sq[DH + j], v * v);
}
__global__ void __launch_bounds__(256) k_hg1(const float* __restrict__ Wh1,
                                             const float* __restrict__ bh1) {
    __shared__ float sx[DH];
    int g = blockIdx.x, j = threadIdx.x;
    sx[j] = g_ha[j] * g_h0[g * DH + j] + g_hc[j];
    __syncthreads();
    float acc = bh1[j];
#pragma unroll 8
    for (int k = 0; k < DH; k++) acc = fmaf(sx[k], Wh1[k * DH + j], acc);
    float v = fmaxf(acc, 0.f);
    g_h1[g * DH + j] = v;
    atomicAdd(&g_sq[2 * DH + j], v);
    atomicAdd(&g_sq[3 * DH + j], v * v);
}
__global__ void __launch_bounds__(256) k_final(const float* __restrict__ Wout,
                                               const float* __restrict__ bout,
                                               float* __restrict__ out) {
    __shared__ float red[DH];
    int g = blockIdx.x, t = threadIdx.x;
    red[t] = (g_ha[t] * g_h1[g * DH + t] + g_hc[t]) * Wout[t];
    __syncthreads();
    for (int o = DH / 2; o > 0; o >>= 1) {
        if (t < o) red[t] += red[t + o];
        __syncthreads();
    }
    if (t == 0) out[g] = red[0] + bout[0];
}

// ------------------- launch -------------------
extern "C" void kernel_launch(void* const* d_in, const int* in_sizes, int n_in,
                              void* d_out, int out_size) {
    const float* x   = (const float*)d_in[0];
    const int*   ei  = (const int*)d_in[1];
    const int*   bat = (const int*)d_in[2];
    const float* Wc  = (const float*)d_in[3];
    const float* bc  = (const float*)d_in[4];
    const float* gc  = (const float*)d_in[5];
    const float* bec = (const float*)d_in[6];
    const float* Wh0 = (const float*)d_in[7];
    const float* bh0 = (const float*)d_in[8];
    const float* gh0 = (const float*)d_in[9];
    const float* beh0= (const float*)d_in[10];
    const float* Wh1 = (const float*)d_in[11];
    const float* bh1 = (const float*)d_in[12];
    const float* gh1 = (const float*)d_in[13];
    const float* beh1= (const float*)d_in[14];
    const float* Wout= (const float*)d_in[15];
    const float* bout= (const float*)d_in[16];
    float* out = (float*)d_out;

    const int* src = ei;
    const int* dst = ei + NE;

    float *p_x0, *p_x1, *p_h, *p_Wmod, *p_dvec, *p_bnsum, *p_bnsq;
    float *p_affa, *p_affc, *p_sq, *p_ha, *p_hc;
    cudaGetSymbolAddress((void**)&p_x0,   g_x0);
    cudaGetSymbolAddress((void**)&p_x1,   g_x1);
    cudaGetSymbolAddress((void**)&p_h,    g_h);
    cudaGetSymbolAddress((void**)&p_Wmod, g_Wmod);
    cudaGetSymbolAddress((void**)&p_dvec, g_dvec);
    cudaGetSymbolAddress((void**)&p_bnsum,g_bnsum);
    cudaGetSymbolAddress((void**)&p_bnsq, g_bnsq);
    cudaGetSymbolAddress((void**)&p_affa, g_affa);
    cudaGetSymbolAddress((void**)&p_affc, g_affc);
    cudaGetSymbolAddress((void**)&p_sq,   g_sq);
    cudaGetSymbolAddress((void**)&p_ha,   g_ha);
    cudaGetSymbolAddress((void**)&p_hc,   g_hc);

    const int T = 256;
    const int gemmBlocks = (NN + 127) / 128;

    // ---- init + CSR build + degree ----
    k_init<<<(INIT_TOT + T - 1) / T, T>>>();
    k_hist<<<(NE + T - 1) / T, T>>>(dst);
    k_dinv<<<(NN + T - 1) / T, T>>>();
    k_scanA<<<SB, 256>>>();
    k_scanB<<<1, 512>>>();
    k_scanC<<<SB, 256>>>();
    k_fill<<<(NE + T - 1) / T, T>>>(src, dst);

    // ---- conv layer 0 ----
    k_sgemm<<<gemmBlocks, T>>>(x, Wc, nullptr, p_h, NN);
    k_agg<<<2048, T>>>(p_h, bc, p_x0, p_bnsum, p_bnsq);
    k_bnaff<<<1, DF>>>(p_bnsum, p_bnsq, gc, bec, p_affa, p_affc, DF, 1.0f / NN);

    // ---- conv layer 1 (BN0 folded into GEMM) ----
    k_wprep<<<65, T>>>(Wc + DF * DF);
    k_sgemm<<<gemmBlocks, T>>>(p_x0, p_Wmod, p_dvec, p_h, NN);
    k_agg<<<2048, T>>>(p_h, bc + DF, p_x1, p_bnsum + DF, p_bnsq + DF);
    k_bnaff<<<1, DF>>>(p_bnsum + DF, p_bnsq + DF, gc + DF, bec + DF, p_affa, p_affc, DF, 1.0f / NN);

    // ---- conv layer 2 ----
    k_wprep<<<65, T>>>(Wc + 2 * DF * DF);
    k_sgemm<<<gemmBlocks, T>>>(p_x1, p_Wmod, p_dvec, p_h, NN);
    k_agg<<<2048, T>>>(p_h, bc + 2 * DF, p_x0, p_bnsum + 2 * DF, p_bnsq + 2 * DF);
    k_bnaff<<<1, DF>>>(p_bnsum + 2 * DF, p_bnsq + 2 * DF, gc + 2 * DF, bec + 2 * DF, p_affa, p_affc, DF, 1.0f / NN);

    // ---- pool (BN2 applied in head gemm0 via g_affa/g_affc) ----
    k_pool<<<128, T>>>(p_x0, bat);

    // ---- head ----
    k_hg0<<<NG, DH>>>(Wh0, bh0);
    k_bnaff<<<1, DH>>>(p_sq, p_sq + DH, gh0, beh0, p_ha, p_hc, DH, 1.0f / NG);
    k_hg1<<<NG, DH>>>(Wh1, bh1);
    k_bnaff<<<1, DH>>>(p_sq + 2 * DH, p_sq + 3 * DH, gh1, beh1, p_ha, p_hc, DH, 1.0f / NG);
    k_final<<<NG, DH>>>(Wout, bout, out);
}

// round 8
// speedup vs baseline: 1.7017x; 1.1326x over previous
#include <cuda_runtime.h>
#include <cuda_bf16.h>
#include <math.h>
#include <stdint.h>

#define NN 100000
#define NE 1600000
#define DF 128
#define NG 512
#define DH 256
#define SB ((NN + 255) / 256)   // 391 scan blocks

// ------------------- scratch (__device__ globals; no allocation) -------------------
static __device__ int   g_cnt[NN];
static __device__ int   g_wptr[NN];
static __device__ int   g_rowptr[NN + 1];
static __device__ int   g_bsum[512];
static __device__ int   g_boff[512];
static __device__ int   g_col[NE];
static __device__ float g_dinv[NN];
static __device__ __align__(16) float g_x0[(size_t)NN * DF];
static __device__ __align__(16) float g_x1[(size_t)NN * DF];
static __device__ __align__(16) float g_h [(size_t)NN * DF];
static __device__ __align__(16) __nv_bfloat16 g_Whi[DF * DF];  // [n][k]
static __device__ __align__(16) __nv_bfloat16 g_Wlo[DF * DF];  // [n][k]
static __device__ __align__(16) float g_dvec[DF];
static __device__ float g_bnsum[3 * DF];
static __device__ float g_bnsq [3 * DF];
static __device__ float g_affa[DF];
static __device__ float g_affc[DF];
static __device__ __align__(16) float g_pool[NG * DF];
static __device__ float g_gcnt[NG];
static __device__ float g_h0[NG * DH];
static __device__ float g_h1[NG * DH];
static __device__ float g_sq[4 * DH];
static __device__ float g_ha[DH];
static __device__ float g_hc[DH];

// ------------------- one-shot init -------------------
#define INIT_TOT (NN + 3 * DF * 2 + NG * DF + NG + 4 * DH)
__global__ void k_init() {
    int i = blockIdx.x * blockDim.x + threadIdx.x;
    if (i < NN) { g_cnt[i] = 0; return; }
    i -= NN;
    if (i < 3 * DF) { g_bnsum[i] = 0.f; return; }
    i -= 3 * DF;
    if (i < 3 * DF) { g_bnsq[i] = 0.f; return; }
    i -= 3 * DF;
    if (i < NG * DF) { g_pool[i] = 0.f; return; }
    i -= NG * DF;
    if (i < NG) { g_gcnt[i] = 0.f; return; }
    i -= NG;
    if (i < 4 * DH) g_sq[i] = 0.f;
}

// ------------------- CSR build -------------------
__global__ void k_hist(const int* __restrict__ dst) {
    int e = blockIdx.x * blockDim.x + threadIdx.x;
    if (e < NE) atomicAdd(&g_cnt[dst[e]], 1);
}
__global__ void k_dinv() {
    int v = blockIdx.x * blockDim.x + threadIdx.x;
    if (v < NN) g_dinv[v] = rsqrtf((float)g_cnt[v] + 1.0f);
}
__global__ void __launch_bounds__(256) k_scanA() {
    __shared__ int s[256];
    int t = threadIdx.x;
    int i = blockIdx.x * 256 + t;
    int v = (i < NN) ? g_cnt[i] : 0;
    s[t] = v;
    __syncthreads();
#pragma unroll
    for (int off = 1; off < 256; off <<= 1) {
        int u = (t >= off) ? s[t - off] : 0;
        __syncthreads();
        s[t] += u;
        __syncthreads();
    }
    if (i < NN) g_rowptr[i] = s[t] - v;
    if (t == 255) g_bsum[blockIdx.x] = s[255];
}
__global__ void __launch_bounds__(512) k_scanB() {
    __shared__ int s[512];
    int t = threadIdx.x;
    int v = (t < SB) ? g_bsum[t] : 0;
    s[t] = v;
    __syncthreads();
#pragma unroll
    for (int off = 1; off < 512; off <<= 1) {
        int u = (t >= off) ? s[t - off] : 0;
        __syncthreads();
        s[t] += u;
        __syncthreads();
    }
    g_boff[t] = s[t] - v;
    if (t == 0) g_rowptr[NN] = NE;
}
__global__ void __launch_bounds__(256) k_scanC() {
    int i = blockIdx.x * 256 + threadIdx.x;
    if (i < NN) {
        int r = g_rowptr[i] + g_boff[blockIdx.x];
        g_rowptr[i] = r;
        g_wptr[i]   = r;
    }
}
__global__ void k_fill(const int* __restrict__ src, const int* __restrict__ dst) {
    int e = blockIdx.x * blockDim.x + threadIdx.x;
    if (e < NE) {
        int v = dst[e];
        int pos = atomicAdd(&g_wptr[v], 1);
        g_col[pos] = src[e];
    }
}

// ------------------- mma.sync helpers -------------------
__device__ __forceinline__ uint32_t smem_u32(const void* p) {
    uint32_t a;
    asm("{ .reg .u64 t; cvta.to.shared.u64 t, %1; cvt.u32.u64 %0, t; }" : "=r"(a) : "l"(p));
    return a;
}
#define LDMX4(r, addr) \
    asm volatile("ldmatrix.sync.aligned.m8n8.x4.shared.b16 {%0,%1,%2,%3}, [%4];" \
        : "=r"((r)[0]), "=r"((r)[1]), "=r"((r)[2]), "=r"((r)[3]) : "r"(addr))
#define MMA_BF16(c, a, b0, b1) \
    asm volatile("mma.sync.aligned.m16n8k16.row.col.f32.bf16.bf16.f32 " \
        "{%0,%1,%2,%3}, {%4,%5,%6,%7}, {%8,%9}, {%0,%1,%2,%3};" \
        : "+f"((c)[0]), "+f"((c)[1]), "+f"((c)[2]), "+f"((c)[3]) \
        : "r"((a)[0]), "r"((a)[1]), "r"((a)[2]), "r"((a)[3]), "r"(b0), "r"(b1))

__device__ __forceinline__ void split8(const float* f, uint4& hi, uint4& lo) {
    uint32_t h[4], l[4];
#pragma unroll
    for (int p = 0; p < 4; p++) {
        __nv_bfloat16 h0 = __float2bfloat16(f[2 * p]);
        __nv_bfloat16 h1 = __float2bfloat16(f[2 * p + 1]);
        __nv_bfloat16 l0 = __float2bfloat16(f[2 * p]     - __bfloat162float(h0));
        __nv_bfloat16 l1 = __float2bfloat16(f[2 * p + 1] - __bfloat162float(h1));
        h[p] = (uint32_t)__bfloat16_as_ushort(h0) | ((uint32_t)__bfloat16_as_ushort(h1) << 16);
        l[p] = (uint32_t)__bfloat16_as_ushort(l0) | ((uint32_t)__bfloat16_as_ushort(l1) << 16);
    }
    hi = make_uint4(h[0], h[1], h[2], h[3]);
    lo = make_uint4(l[0], l[1], l[2], l[3]);
}

// ------------------- tensor-core GEMM: C[M,128] = A[M,128] @ W + dvec ---------------
// A fp32 split to bf16 hi/lo in SMEM; W pre-split as Whi/Wlo [n][k].
// 256 threads = 8 warps (4m x 2n); warp tile m32 x n64; SMEM 128KB, 1 CTA/SM.
#define SMO_AHI 0
#define SMO_ALO 32768
#define SMO_BHI 65536
#define SMO_BLO 98304
#define SM_TOT  131072

__global__ void __launch_bounds__(256) k_mmagemm(
    const float* __restrict__ A,
    const __nv_bfloat16* __restrict__ Bhi, const __nv_bfloat16* __restrict__ Blo,
    const float* __restrict__ dvec, float* __restrict__ C, int M)
{
    extern __shared__ char sm[];
    uint32_t sbase = smem_u32(sm);
    int tid = threadIdx.x, lane = tid & 31, wid = tid >> 5;
    int warpM = wid & 3, warpN = wid >> 2;   // 4 x 2
    int row0 = blockIdx.x * 128;

    // stage B (bf16 [n][k]) with XOR swizzle: chunk' = chunk ^ (row&7)
    for (int i = tid; i < 2048; i += 256) {
        int n = i >> 4, c = i & 15;
        uint32_t off = n * 256 + (uint32_t)((c ^ (n & 7)) << 4);
        *(uint4*)(sm + SMO_BHI + off) = *(const uint4*)(Bhi + n * 128 + c * 8);
        *(uint4*)(sm + SMO_BLO + off) = *(const uint4*)(Blo + n * 128 + c * 8);
    }
    // stage + split A
    for (int i = tid; i < 2048; i += 256) {
        int m = i >> 4, c = i & 15;
        int row = row0 + m;
        float f[8];
        if (row < M) {
            float4 f0 = *(const float4*)(A + (size_t)row * 128 + c * 8);
            float4 f1 = *(const float4*)(A + (size_t)row * 128 + c * 8 + 4);
            f[0] = f0.x; f[1] = f0.y; f[2] = f0.z; f[3] = f0.w;
            f[4] = f1.x; f[5] = f1.y; f[6] = f1.z; f[7] = f1.w;
        } else {
#pragma unroll
            for (int p = 0; p < 8; p++) f[p] = 0.f;
        }
        uint4 hi, lo;
        split8(f, hi, lo);
        uint32_t off = m * 256 + (uint32_t)((c ^ (m & 7)) << 4);
        *(uint4*)(sm + SMO_AHI + off) = hi;
        *(uint4*)(sm + SMO_ALO + off) = lo;
    }
    __syncthreads();

    float acc[2][8][4];
#pragma unroll
    for (int i = 0; i < 2; i++)
#pragma unroll
        for (int j = 0; j < 8; j++)
#pragma unroll
            for (int q = 0; q < 4; q++) acc[i][j][q] = 0.f;

    // A-frag lane addressing: row = base + (lane&15), k = K0 + ((lane>>4)<<3)
    int a_mrow0 = warpM * 32 + (lane & 15);
    int a_kadd  = (lane >> 4) << 3;
    // B-frag lane addressing: n = base + (lane&7) + ((lane>>4)<<3), k = K0 + (((lane>>3)&1)<<3)
    int b_nadd  = (lane & 7) + ((lane >> 4) << 3);
    int b_kadd  = ((lane >> 3) & 1) << 3;

#pragma unroll
    for (int ks = 0; ks < 8; ks++) {
        int K0 = ks * 16;
        uint32_t ahi[2][4], alo[2][4];
#pragma unroll
        for (int fm = 0; fm < 2; fm++) {
            int mrow = a_mrow0 + fm * 16;
            int kk = K0 + a_kadd;
            uint32_t off = mrow * 256 + (uint32_t)((((kk >> 3) ^ (mrow & 7)) << 4));
            LDMX4(ahi[fm], sbase + SMO_AHI + off);
            LDMX4(alo[fm], sbase + SMO_ALO + off);
        }
#pragma unroll
        for (int nb = 0; nb < 4; nb++) {
            int nrow = warpN * 64 + nb * 16 + b_nadd;
            int kk = K0 + b_kadd;
            uint32_t off = nrow * 256 + (uint32_t)((((kk >> 3) ^ (nrow & 7)) << 4));
            uint32_t bhi[4], blo[4];
            LDMX4(bhi, sbase + SMO_BHI + off);
            LDMX4(blo, sbase + SMO_BLO + off);
#pragma unroll
            for (int fm = 0; fm < 2; fm++) {
                MMA_BF16(acc[fm][nb * 2 + 0], ahi[fm], bhi[0], bhi[1]);
                MMA_BF16(acc[fm][nb * 2 + 1], ahi[fm], bhi[2], bhi[3]);
            }
#pragma unroll
            for (int fm = 0; fm < 2; fm++) {
                MMA_BF16(acc[fm][nb * 2 + 0], ahi[fm], blo[0], blo[1]);
                MMA_BF16(acc[fm][nb * 2 + 1], ahi[fm], blo[2], blo[3]);
            }
#pragma unroll
            for (int fm = 0; fm < 2; fm++) {
                MMA_BF16(acc[fm][nb * 2 + 0], alo[fm], bhi[0], bhi[1]);
                MMA_BF16(acc[fm][nb * 2 + 1], alo[fm], bhi[2], bhi[3]);
            }
        }
    }

    // epilogue: c0,c1 -> (row, col..col+1); c2,c3 -> (row+8, ...)
#pragma unroll
    for (int fm = 0; fm < 2; fm++) {
#pragma unroll
        for (int nf = 0; nf < 8; nf++) {
            int r = row0 + warpM * 32 + fm * 16 + (lane >> 2);
            int col = warpN * 64 + nf * 8 + (lane & 3) * 2;
            float d0 = dvec ? dvec[col] : 0.f;
            float d1 = dvec ? dvec[col + 1] : 0.f;
            if (r < M)
                *(float2*)(C + (size_t)r * 128 + col) =
                    make_float2(acc[fm][nf][0] + d0, acc[fm][nf][1] + d1);
            if (r + 8 < M)
                *(float2*)(C + (size_t)(r + 8) * 128 + col) =
                    make_float2(acc[fm][nf][2] + d0, acc[fm][nf][3] + d1);
        }
    }
}

// ------------------- W prep: Whi/Wlo[n][k] = split(a[k]*W[k][n]); +dvec ------------
__global__ void k_wprep(const float* __restrict__ W, int useA) {
    if (blockIdx.x < 64) {
        int i = blockIdx.x * 256 + threadIdx.x;   // 0..16383
        int n = i >> 7, k = i & 127;
        float a = useA ? g_affa[k] : 1.0f;
        float w = a * W[k * DF + n];
        __nv_bfloat16 hi = __float2bfloat16(w);
        __nv_bfloat16 lo = __float2bfloat16(w - __bfloat162float(hi));
        g_Whi[n * DF + k] = hi;
        g_Wlo[n * DF + k] = lo;
    } else if (useA) {
        int j = threadIdx.x;
        if (j < DF) {
            float s = 0.f;
#pragma unroll 8
            for (int k = 0; k < DF; k++) s = fmaf(g_affc[k], W[k * DF + j], s);
            g_dvec[j] = s;
        }
    }
}

// ------------------- GCN aggregation + bias + relu + fused BN stats -----------------
__global__ void __launch_bounds__(256) k_agg(
    const float* __restrict__ h, const float* __restrict__ bias,
    float* __restrict__ xout, float* __restrict__ bnsum, float* __restrict__ bnsq)
{
    __shared__ float bs[DF], bq[DF];
    int tid = threadIdx.x;
    if (tid < DF) { bs[tid] = 0.f; bq[tid] = 0.f; }
    __syncthreads();

    int lane = tid & 31;
    int w    = tid >> 5;
    int warpId = blockIdx.x * (blockDim.x >> 5) + w;
    int nW     = gridDim.x * (blockDim.x >> 5);

    float4 bv = *(const float4*)(bias + lane * 4);
    float ls0 = 0, ls1 = 0, ls2 = 0, ls3 = 0;
    float lq0 = 0, lq1 = 0, lq2 = 0, lq3 = 0;

    for (int v = warpId; v < NN; v += nW) {
        float dv = g_dinv[v];
        float4 hv = *((const float4*)(h + (size_t)v * DF) + lane);
        float ax = hv.x * dv, ay = hv.y * dv, az = hv.z * dv, aw = hv.w * dv;

        int beg = g_rowptr[v], end = g_rowptr[v + 1];
        for (int e0 = beg; e0 < end; e0 += 32) {
            int idx = e0 + lane;
            int   sl = (idx < end) ? g_col[idx]  : 0;
            float dl = (idx < end) ? g_dinv[sl]  : 0.f;
            int m = end - e0; if (m > 32) m = 32;
            for (int j = 0; j < m; j++) {
                int   sj  = __shfl_sync(0xffffffffu, sl, j);
                float dsj = __shfl_sync(0xffffffffu, dl, j);
                float4 hs = *((const float4*)(h + (size_t)sj * DF) + lane);
                ax = fmaf(hs.x, dsj, ax);
                ay = fmaf(hs.y, dsj, ay);
                az = fmaf(hs.z, dsj, az);
                aw = fmaf(hs.w, dsj, aw);
            }
        }
        float ox = fmaxf(fmaf(ax, dv, bv.x), 0.f);
        float oy = fmaxf(fmaf(ay, dv, bv.y), 0.f);
        float oz = fmaxf(fmaf(az, dv, bv.z), 0.f);
        float ow = fmaxf(fmaf(aw, dv, bv.w), 0.f);
        *((float4*)(xout + (size_t)v * DF) + lane) = make_float4(ox, oy, oz, ow);
        ls0 += ox; lq0 += ox * ox;
        ls1 += oy; lq1 += oy * oy;
        ls2 += oz; lq2 += oz * oz;
        ls3 += ow; lq3 += ow * ow;
    }
    atomicAdd(&bs[lane * 4 + 0], ls0); atomicAdd(&bq[lane * 4 + 0], lq0);
    atomicAdd(&bs[lane * 4 + 1], ls1); atomicAdd(&bq[lane * 4 + 1], lq1);
    atomicAdd(&bs[lane * 4 + 2], ls2); atomicAdd(&bq[lane * 4 + 2], lq2);
    atomicAdd(&bs[lane * 4 + 3], ls3); atomicAdd(&bq[lane * 4 + 3], lq3);
    __syncthreads();
    if (tid < DF) {
        atomicAdd(&bnsum[tid], bs[tid]);
        atomicAdd(&bnsq[tid],  bq[tid]);
    }
}

// ------------------- BN affine params -------------------
__global__ void k_bnaff(const float* __restrict__ sum, const float* __restrict__ sq,
                        const float* __restrict__ gamma, const float* __restrict__ beta,
                        float* __restrict__ a, float* __restrict__ c,
                        int D, float invN)
{
    int j = blockIdx.x * blockDim.x + threadIdx.x;
    if (j >= D) return;
    float m   = sum[j] * invN;
    float var = sq[j] * invN - m * m;
    float aj  = gamma[j] * rsqrtf(var + 1e-5f);
    a[j] = aj;
    c[j] = beta[j] - aj * m;
}

// ------------------- global_add_pool -------------------
__global__ void k_pool(const float* __restrict__ x, const int* __restrict__ batch) {
    int lane = threadIdx.x & 31;
    int w    = (blockIdx.x * blockDim.x + threadIdx.x) >> 5;
    int nW   = (gridDim.x * blockDim.x) >> 5;
    int C    = (NN + nW - 1) / nW;
    int beg = w * C;
    int end = beg + C; if (end > NN) end = NN;
    if (beg >= end) return;

    float a0 = 0, a1 = 0, a2 = 0, a3 = 0, cntf = 0;
    int cur = batch[beg];
    for (int v = beg; v < end; v++) {
        int g = batch[v];
        if (g != cur) {
            atomicAdd(&g_pool[cur * DF + lane * 4 + 0], a0);
            atomicAdd(&g_pool[cur * DF + lane * 4 + 1], a1);
            atomicAdd(&g_pool[cur * DF + lane * 4 + 2], a2);
            atomicAdd(&g_pool[cur * DF + lane * 4 + 3], a3);
            if (lane == 0) atomicAdd(&g_gcnt[cur], cntf);
            a0 = a1 = a2 = a3 = 0.f; cntf = 0.f; cur = g;
        }
        float4 xv = *((const float4*)(x + (size_t)v * DF) + lane);
        a0 += xv.x; a1 += xv.y; a2 += xv.z; a3 += xv.w; cntf += 1.f;
    }
    atomicAdd(&g_pool[cur * DF + lane * 4 + 0], a0);
    atomicAdd(&g_pool[cur * DF + lane * 4 + 1], a1);
    atomicAdd(&g_pool[cur * DF + lane * 4 + 2], a2);
    atomicAdd(&g_pool[cur * DF + lane * 4 + 3], a3);
    if (lane == 0) atomicAdd(&g_gcnt[cur], cntf);
}

// ------------------- head -------------------
__global__ void __launch_bounds__(256) k_hg0(const float* __restrict__ Wh0,
                                             const float* __restrict__ bh0) {
    __shared__ float sx[DF];
    int g = blockIdx.x, j = threadIdx.x;
    if (j < DF) sx[j] = g_affa[j] * g_pool[g * DF + j] + g_affc[j] * g_gcnt[g];
    __syncthreads();
    float acc = bh0[j];
#pragma unroll 8
    for (int k = 0; k < DF; k++) acc = fmaf(sx[k], Wh0[k * DH + j], acc);
    float v = fmaxf(acc, 0.f);
    g_h0[g * DH + j] = v;
    atomicAdd(&g_sq[j], v);
    atomicAdd(&g_sq[DH + j], v * v);
}
__global__ void __launch_bounds__(256) k_hg1(const float* __restrict__ Wh1,
                                             const float* __restrict__ bh1) {
    __shared__ float sx[DH];
    int g = blockIdx.x, j = threadIdx.x;
    sx[j] = g_ha[j] * g_h0[g * DH + j] + g_hc[j];
    __syncthreads();
    float acc = bh1[j];
#pragma unroll 8
    for (int k = 0; k < DH; k++) acc = fmaf(sx[k], Wh1[k * DH + j], acc);
    float v = fmaxf(acc, 0.f);
    g_h1[g * DH + j] = v;
    atomicAdd(&g_sq[2 * DH + j], v);
    atomicAdd(&g_sq[3 * DH + j], v * v);
}
__global__ void __launch_bounds__(256) k_final(const float* __restrict__ Wout,
                                               const float* __restrict__ bout,
                                               float* __restrict__ out) {
    __shared__ float red[DH];
    int g = blockIdx.x, t = threadIdx.x;
    red[t] = (g_ha[t] * g_h1[g * DH + t] + g_hc[t]) * Wout[t];
    __syncthreads();
    for (int o = DH / 2; o > 0; o >>= 1) {
        if (t < o) red[t] += red[t + o];
        __syncthreads();
    }
    if (t == 0) out[g] = red[0] + bout[0];
}

// ------------------- launch -------------------
extern "C" void kernel_launch(void* const* d_in, const int* in_sizes, int n_in,
                              void* d_out, int out_size) {
    const float* x   = (const float*)d_in[0];
    const int*   ei  = (const int*)d_in[1];
    const int*   bat = (const int*)d_in[2];
    const float* Wc  = (const float*)d_in[3];
    const float* bc  = (const float*)d_in[4];
    const float* gc  = (const float*)d_in[5];
    const float* bec = (const float*)d_in[6];
    const float* Wh0 = (const float*)d_in[7];
    const float* bh0 = (const float*)d_in[8];
    const float* gh0 = (const float*)d_in[9];
    const float* beh0= (const float*)d_in[10];
    const float* Wh1 = (const float*)d_in[11];
    const float* bh1 = (const float*)d_in[12];
    const float* gh1 = (const float*)d_in[13];
    const float* beh1= (const float*)d_in[14];
    const float* Wout= (const float*)d_in[15];
    const float* bout= (const float*)d_in[16];
    float* out = (float*)d_out;

    const int* src = ei;
    const int* dst = ei + NE;

    float *p_x0, *p_x1, *p_h, *p_dvec, *p_bnsum, *p_bnsq;
    float *p_affa, *p_affc, *p_sq, *p_ha, *p_hc;
    __nv_bfloat16 *p_Whi, *p_Wlo;
    cudaGetSymbolAddress((void**)&p_x0,   g_x0);
    cudaGetSymbolAddress((void**)&p_x1,   g_x1);
    cudaGetSymbolAddress((void**)&p_h,    g_h);
    cudaGetSymbolAddress((void**)&p_Whi,  g_Whi);
    cudaGetSymbolAddress((void**)&p_Wlo,  g_Wlo);
    cudaGetSymbolAddress((void**)&p_dvec, g_dvec);
    cudaGetSymbolAddress((void**)&p_bnsum,g_bnsum);
    cudaGetSymbolAddress((void**)&p_bnsq, g_bnsq);
    cudaGetSymbolAddress((void**)&p_affa, g_affa);
    cudaGetSymbolAddress((void**)&p_affc, g_affc);
    cudaGetSymbolAddress((void**)&p_sq,   g_sq);
    cudaGetSymbolAddress((void**)&p_ha,   g_ha);
    cudaGetSymbolAddress((void**)&p_hc,   g_hc);

    cudaFuncSetAttribute(k_mmagemm, cudaFuncAttributeMaxDynamicSharedMemorySize, SM_TOT);

    const int T = 256;
    const int gemmBlocks = (NN + 127) / 128;

    // ---- init + CSR build + degree ----
    k_init<<<(INIT_TOT + T - 1) / T, T>>>();
    k_hist<<<(NE + T - 1) / T, T>>>(dst);
    k_dinv<<<(NN + T - 1) / T, T>>>();
    k_scanA<<<SB, 256>>>();
    k_scanB<<<1, 512>>>();
    k_scanC<<<SB, 256>>>();
    k_fill<<<(NE + T - 1) / T, T>>>(src, dst);

    // ---- conv layer 0 ----
    k_wprep<<<65, T>>>(Wc, 0);
    k_mmagemm<<<gemmBlocks, T, SM_TOT>>>(x, p_Whi, p_Wlo, nullptr, p_h, NN);
    k_agg<<<2048, T>>>(p_h, bc, p_x0, p_bnsum, p_bnsq);
    k_bnaff<<<1, DF>>>(p_bnsum, p_bnsq, gc, bec, p_affa, p_affc, DF, 1.0f / NN);

    // ---- conv layer 1 (BN0 folded) ----
    k_wprep<<<65, T>>>(Wc + DF * DF, 1);
    k_mmagemm<<<gemmBlocks, T, SM_TOT>>>(p_x0, p_Whi, p_Wlo, p_dvec, p_h, NN);
    k_agg<<<2048, T>>>(p_h, bc + DF, p_x1, p_bnsum + DF, p_bnsq + DF);
    k_bnaff<<<1, DF>>>(p_bnsum + DF, p_bnsq + DF, gc + DF, bec + DF, p_affa, p_affc, DF, 1.0f / NN);

    // ---- conv layer 2 ----
    k_wprep<<<65, T>>>(Wc + 2 * DF * DF, 1);
    k_mmagemm<<<gemmBlocks, T, SM_TOT>>>(p_x1, p_Whi, p_Wlo, p_dvec, p_h, NN);
    k_agg<<<2048, T>>>(p_h, bc + 2 * DF, p_x0, p_bnsum + 2 * DF, p_bnsq + 2 * DF);
    k_bnaff<<<1, DF>>>(p_bnsum + 2 * DF, p_bnsq + 2 * DF, gc + 2 * DF, bec + 2 * DF, p_affa, p_affc, DF, 1.0f / NN);

    // ---- pool ----
    k_pool<<<128, T>>>(p_x0, bat);

    // ---- head ----
    k_hg0<<<NG, DH>>>(Wh0, bh0);
    k_bnaff<<<1, DH>>>(p_sq, p_sq + DH, gh0, beh0, p_ha, p_hc, DH, 1.0f / NG);
    k_hg1<<<NG, DH>>>(Wh1, bh1);
    k_bnaff<<<1, DH>>>(p_sq + 2 * DH, p_sq + 3 * DH, gh1, beh1, p_ha, p_hc, DH, 1.0f / NG);
    k_final<<<NG, DH>>>(Wout, bout, out);
}

// round 9
// speedup vs baseline: 1.9128x; 1.1240x over previous
#include <cuda_runtime.h>
#include <cuda_bf16.h>
#include <math.h>
#include <stdint.h>

#define NN 100000
#define NE 1600000
#define DF 128
#define NG 512
#define DH 256
#define SB ((NN + 255) / 256)   // 391 scan blocks

// ------------------- scratch (__device__ globals; no allocation) -------------------
static __device__ int   g_cnt[NN];
static __device__ int   g_wptr[NN];
static __device__ int   g_rowptr[NN + 1];
static __device__ int   g_bsum[512];
static __device__ int   g_boff[512];
static __device__ int   g_col[NE];
static __device__ float g_dinv[NN];
static __device__ __align__(16) float g_x0[(size_t)NN * DF];
static __device__ __align__(16) float g_x1[(size_t)NN * DF];
static __device__ __align__(16) float g_h [(size_t)NN * DF];
static __device__ __align__(16) __nv_bfloat16 g_Whi[DF * DF];  // [n][k]
static __device__ __align__(16) __nv_bfloat16 g_Wlo[DF * DF];  // [n][k]
static __device__ __align__(16) float g_dvec[DF];
static __device__ float g_bnsum[3 * DF];
static __device__ float g_bnsq [3 * DF];
static __device__ float g_affa[DF];
static __device__ float g_affc[DF];
static __device__ __align__(16) float g_pool[NG * DF];
static __device__ float g_gcnt[NG];
static __device__ float g_h0[NG * DH];
static __device__ float g_h1[NG * DH];
static __device__ float g_sq[4 * DH];
static __device__ float g_ha[DH];
static __device__ float g_hc[DH];

// ------------------- one-shot init -------------------
#define INIT_TOT (NN + 3 * DF * 2 + NG * DF + NG + 4 * DH)
__global__ void k_init() {
    int i = blockIdx.x * blockDim.x + threadIdx.x;
    if (i < NN) { g_cnt[i] = 0; return; }
    i -= NN;
    if (i < 3 * DF) { g_bnsum[i] = 0.f; return; }
    i -= 3 * DF;
    if (i < 3 * DF) { g_bnsq[i] = 0.f; return; }
    i -= 3 * DF;
    if (i < NG * DF) { g_pool[i] = 0.f; return; }
    i -= NG * DF;
    if (i < NG) { g_gcnt[i] = 0.f; return; }
    i -= NG;
    if (i < 4 * DH) g_sq[i] = 0.f;
}

// ------------------- CSR build -------------------
__global__ void k_hist(const int* __restrict__ dst) {
    int e = blockIdx.x * blockDim.x + threadIdx.x;
    if (e < NE) atomicAdd(&g_cnt[dst[e]], 1);
}
__global__ void k_dinv() {
    int v = blockIdx.x * blockDim.x + threadIdx.x;
    if (v < NN) g_dinv[v] = rsqrtf((float)g_cnt[v] + 1.0f);
}
__global__ void __launch_bounds__(256) k_scanA() {
    __shared__ int s[256];
    int t = threadIdx.x;
    int i = blockIdx.x * 256 + t;
    int v = (i < NN) ? g_cnt[i] : 0;
    s[t] = v;
    __syncthreads();
#pragma unroll
    for (int off = 1; off < 256; off <<= 1) {
        int u = (t >= off) ? s[t - off] : 0;
        __syncthreads();
        s[t] += u;
        __syncthreads();
    }
    if (i < NN) g_rowptr[i] = s[t] - v;
    if (t == 255) g_bsum[blockIdx.x] = s[255];
}
__global__ void __launch_bounds__(512) k_scanB() {
    __shared__ int s[512];
    int t = threadIdx.x;
    int v = (t < SB) ? g_bsum[t] : 0;
    s[t] = v;
    __syncthreads();
#pragma unroll
    for (int off = 1; off < 512; off <<= 1) {
        int u = (t >= off) ? s[t - off] : 0;
        __syncthreads();
        s[t] += u;
        __syncthreads();
    }
    g_boff[t] = s[t] - v;
    if (t == 0) g_rowptr[NN] = NE;
}
__global__ void __launch_bounds__(256) k_scanC() {
    int i = blockIdx.x * 256 + threadIdx.x;
    if (i < NN) {
        int r = g_rowptr[i] + g_boff[blockIdx.x];
        g_rowptr[i] = r;
        g_wptr[i]   = r;
    }
}
__global__ void k_fill(const int* __restrict__ src, const int* __restrict__ dst) {
    int e = blockIdx.x * blockDim.x + threadIdx.x;
    if (e < NE) {
        int v = dst[e];
        int pos = atomicAdd(&g_wptr[v], 1);
        g_col[pos] = src[e];
    }
}

// ------------------- mma.sync helpers -------------------
__device__ __forceinline__ uint32_t smem_u32(const void* p) {
    uint32_t a;
    asm("{ .reg .u64 t; cvta.to.shared.u64 t, %1; cvt.u32.u64 %0, t; }" : "=r"(a) : "l"(p));
    return a;
}
#define LDMX4(r, addr) \
    asm volatile("ldmatrix.sync.aligned.m8n8.x4.shared.b16 {%0,%1,%2,%3}, [%4];" \
        : "=r"((r)[0]), "=r"((r)[1]), "=r"((r)[2]), "=r"((r)[3]) : "r"(addr))
#define MMA_BF16(c, a, b0, b1) \
    asm volatile("mma.sync.aligned.m16n8k16.row.col.f32.bf16.bf16.f32 " \
        "{%0,%1,%2,%3}, {%4,%5,%6,%7}, {%8,%9}, {%0,%1,%2,%3};" \
        : "+f"((c)[0]), "+f"((c)[1]), "+f"((c)[2]), "+f"((c)[3]) \
        : "r"((a)[0]), "r"((a)[1]), "r"((a)[2]), "r"((a)[3]), "r"(b0), "r"(b1))

__device__ __forceinline__ void split8(const float* f, uint4& hi, uint4& lo) {
    uint32_t h[4], l[4];
#pragma unroll
    for (int p = 0; p < 4; p++) {
        __nv_bfloat16 h0 = __float2bfloat16(f[2 * p]);
        __nv_bfloat16 h1 = __float2bfloat16(f[2 * p + 1]);
        __nv_bfloat16 l0 = __float2bfloat16(f[2 * p]     - __bfloat162float(h0));
        __nv_bfloat16 l1 = __float2bfloat16(f[2 * p + 1] - __bfloat162float(h1));
        h[p] = (uint32_t)__bfloat16_as_ushort(h0) | ((uint32_t)__bfloat16_as_ushort(h1) << 16);
        l[p] = (uint32_t)__bfloat16_as_ushort(l0) | ((uint32_t)__bfloat16_as_ushort(l1) << 16);
    }
    hi = make_uint4(h[0], h[1], h[2], h[3]);
    lo = make_uint4(l[0], l[1], l[2], l[3]);
}

// ------------------- tensor-core GEMM: C[M,128] = A[M,128] @ W + dvec ---------------
// Tile M=64 x N=128 x K=128. SMEM 96KB -> 2 CTAs/SM. 8 warps: 2m x 4n, warp m32 x n32.
#define SMO_AHI 0
#define SMO_ALO 16384
#define SMO_BHI 32768
#define SMO_BLO 65536
#define SM_TOT  98304

__global__ void __launch_bounds__(256) k_mmagemm(
    const float* __restrict__ A,
    const __nv_bfloat16* __restrict__ Bhi, const __nv_bfloat16* __restrict__ Blo,
    const float* __restrict__ dvec, float* __restrict__ C, int M)
{
    extern __shared__ char sm[];
    uint32_t sbase = smem_u32(sm);
    int tid = threadIdx.x, lane = tid & 31, wid = tid >> 5;
    int warpM = wid & 1, warpN = wid >> 1;   // 2 x 4
    int row0 = blockIdx.x * 64;

    // stage B (bf16 [n][k]) with XOR swizzle: chunk' = chunk ^ (row&7)
    for (int i = tid; i < 2048; i += 256) {
        int n = i >> 4, c = i & 15;
        uint32_t off = n * 256 + (uint32_t)((c ^ (n & 7)) << 4);
        *(uint4*)(sm + SMO_BHI + off) = *(const uint4*)(Bhi + n * 128 + c * 8);
        *(uint4*)(sm + SMO_BLO + off) = *(const uint4*)(Blo + n * 128 + c * 8);
    }
    // stage + split A (64 rows)
    for (int i = tid; i < 1024; i += 256) {
        int m = i >> 4, c = i & 15;
        int row = row0 + m;
        float f[8];
        if (row < M) {
            float4 f0 = *(const float4*)(A + (size_t)row * 128 + c * 8);
            float4 f1 = *(const float4*)(A + (size_t)row * 128 + c * 8 + 4);
            f[0] = f0.x; f[1] = f0.y; f[2] = f0.z; f[3] = f0.w;
            f[4] = f1.x; f[5] = f1.y; f[6] = f1.z; f[7] = f1.w;
        } else {
#pragma unroll
            for (int p = 0; p < 8; p++) f[p] = 0.f;
        }
        uint4 hi, lo;
        split8(f, hi, lo);
        uint32_t off = m * 256 + (uint32_t)((c ^ (m & 7)) << 4);
        *(uint4*)(sm + SMO_AHI + off) = hi;
        *(uint4*)(sm + SMO_ALO + off) = lo;
    }
    __syncthreads();

    float acc[2][4][4];
#pragma unroll
    for (int i = 0; i < 2; i++)
#pragma unroll
        for (int j = 0; j < 4; j++)
#pragma unroll
            for (int q = 0; q < 4; q++) acc[i][j][q] = 0.f;

    int a_mrow0 = warpM * 32 + (lane & 15);
    int a_kadd  = (lane >> 4) << 3;
    int b_nadd  = (lane & 7) + ((lane >> 4) << 3);
    int b_kadd  = ((lane >> 3) & 1) << 3;

#pragma unroll
    for (int ks = 0; ks < 8; ks++) {
        int K0 = ks * 16;
        uint32_t ahi[2][4], alo[2][4];
#pragma unroll
        for (int fm = 0; fm < 2; fm++) {
            int mrow = a_mrow0 + fm * 16;
            int kk = K0 + a_kadd;
            uint32_t off = mrow * 256 + (uint32_t)((((kk >> 3) ^ (mrow & 7)) << 4));
            LDMX4(ahi[fm], sbase + SMO_AHI + off);
            LDMX4(alo[fm], sbase + SMO_ALO + off);
        }
#pragma unroll
        for (int nb = 0; nb < 2; nb++) {
            int nrow = warpN * 32 + nb * 16 + b_nadd;
            int kk = K0 + b_kadd;
            uint32_t off = nrow * 256 + (uint32_t)((((kk >> 3) ^ (nrow & 7)) << 4));
            uint32_t bhi[4], blo[4];
            LDMX4(bhi, sbase + SMO_BHI + off);
            LDMX4(blo, sbase + SMO_BLO + off);
#pragma unroll
            for (int fm = 0; fm < 2; fm++) {
                MMA_BF16(acc[fm][nb * 2 + 0], ahi[fm], bhi[0], bhi[1]);
                MMA_BF16(acc[fm][nb * 2 + 1], ahi[fm], bhi[2], bhi[3]);
            }
#pragma unroll
            for (int fm = 0; fm < 2; fm++) {
                MMA_BF16(acc[fm][nb * 2 + 0], ahi[fm], blo[0], blo[1]);
                MMA_BF16(acc[fm][nb * 2 + 1], ahi[fm], blo[2], blo[3]);
            }
#pragma unroll
            for (int fm = 0; fm < 2; fm++) {
                MMA_BF16(acc[fm][nb * 2 + 0], alo[fm], bhi[0], bhi[1]);
                MMA_BF16(acc[fm][nb * 2 + 1], alo[fm], bhi[2], bhi[3]);
            }
        }
    }

    // epilogue
#pragma unroll
    for (int fm = 0; fm < 2; fm++) {
#pragma unroll
        for (int nf = 0; nf < 4; nf++) {
            int r = row0 + warpM * 32 + fm * 16 + (lane >> 2);
            int col = warpN * 32 + nf * 8 + (lane & 3) * 2;
            float d0 = dvec ? dvec[col] : 0.f;
            float d1 = dvec ? dvec[col + 1] : 0.f;
            if (r < M)
                *(float2*)(C + (size_t)r * 128 + col) =
                    make_float2(acc[fm][nf][0] + d0, acc[fm][nf][1] + d1);
            if (r + 8 < M)
                *(float2*)(C + (size_t)(r + 8) * 128 + col) =
                    make_float2(acc[fm][nf][2] + d0, acc[fm][nf][3] + d1);
        }
    }
}

// ------------------- W prep: Whi/Wlo[n][k] = split(a[k]*W[k][n]); +dvec ------------
__global__ void k_wprep(const float* __restrict__ W, int useA) {
    if (blockIdx.x < 64) {
        int i = blockIdx.x * 256 + threadIdx.x;   // 0..16383
        int n = i >> 7, k = i & 127;
        float a = useA ? g_affa[k] : 1.0f;
        float w = a * W[k * DF + n];
        __nv_bfloat16 hi = __float2bfloat16(w);
        __nv_bfloat16 lo = __float2bfloat16(w - __bfloat162float(hi));
        g_Whi[n * DF + k] = hi;
        g_Wlo[n * DF + k] = lo;
    } else if (useA) {
        int j = threadIdx.x;
        if (j < DF) {
            float s = 0.f;
#pragma unroll 8
            for (int k = 0; k < DF; k++) s = fmaf(g_affc[k], W[k * DF + j], s);
            g_dvec[j] = s;
        }
    }
}

// ------------------- GCN aggregation + bias + relu + fused BN stats -----------------
__global__ void __launch_bounds__(256) k_agg(
    const float* __restrict__ h, const float* __restrict__ bias,
    float* __restrict__ xout, float* __restrict__ bnsum, float* __restrict__ bnsq)
{
    __shared__ float bs[DF], bq[DF];
    int tid = threadIdx.x;
    if (tid < DF) { bs[tid] = 0.f; bq[tid] = 0.f; }
    __syncthreads();

    int lane = tid & 31;
    int w    = tid >> 5;
    int warpId = blockIdx.x * (blockDim.x >> 5) + w;
    int nW     = gridDim.x * (blockDim.x >> 5);

    float4 bv = *(const float4*)(bias + lane * 4);
    float ls0 = 0, ls1 = 0, ls2 = 0, ls3 = 0;
    float lq0 = 0, lq1 = 0, lq2 = 0, lq3 = 0;

    for (int v = warpId; v < NN; v += nW) {
        float dv = g_dinv[v];
        float4 hv = *((const float4*)(h + (size_t)v * DF) + lane);
        float ax = hv.x * dv, ay = hv.y * dv, az = hv.z * dv, aw = hv.w * dv;

        int beg = g_rowptr[v], end = g_rowptr[v + 1];
        for (int e0 = beg; e0 < end; e0 += 32) {
            int idx = e0 + lane;
            int   sl = (idx < end) ? g_col[idx]  : 0;
            float dl = (idx < end) ? g_dinv[sl]  : 0.f;
            int m = end - e0; if (m > 32) m = 32;
            for (int j = 0; j < m; j++) {
                int   sj  = __shfl_sync(0xffffffffu, sl, j);
                float dsj = __shfl_sync(0xffffffffu, dl, j);
                float4 hs = *((const float4*)(h + (size_t)sj * DF) + lane);
                ax = fmaf(hs.x, dsj, ax);
                ay = fmaf(hs.y, dsj, ay);
                az = fmaf(hs.z, dsj, az);
                aw = fmaf(hs.w, dsj, aw);
            }
        }
        float ox = fmaxf(fmaf(ax, dv, bv.x), 0.f);
        float oy = fmaxf(fmaf(ay, dv, bv.y), 0.f);
        float oz = fmaxf(fmaf(az, dv, bv.z), 0.f);
        float ow = fmaxf(fmaf(aw, dv, bv.w), 0.f);
        *((float4*)(xout + (size_t)v * DF) + lane) = make_float4(ox, oy, oz, ow);
        ls0 += ox; lq0 += ox * ox;
        ls1 += oy; lq1 += oy * oy;
        ls2 += oz; lq2 += oz * oz;
        ls3 += ow; lq3 += ow * ow;
    }
    atomicAdd(&bs[lane * 4 + 0], ls0); atomicAdd(&bq[lane * 4 + 0], lq0);
    atomicAdd(&bs[lane * 4 + 1], ls1); atomicAdd(&bq[lane * 4 + 1], lq1);
    atomicAdd(&bs[lane * 4 + 2], ls2); atomicAdd(&bq[lane * 4 + 2], lq2);
    atomicAdd(&bs[lane * 4 + 3], ls3); atomicAdd(&bq[lane * 4 + 3], lq3);
    __syncthreads();
    if (tid < DF) {
        atomicAdd(&bnsum[tid], bs[tid]);
        atomicAdd(&bnsq[tid],  bq[tid]);
    }
}

// ------------------- BN affine params -------------------
__global__ void k_bnaff(const float* __restrict__ sum, const float* __restrict__ sq,
                        const float* __restrict__ gamma, const float* __restrict__ beta,
                        float* __restrict__ a, float* __restrict__ c,
                        int D, float invN)
{
    int j = blockIdx.x * blockDim.x + threadIdx.x;
    if (j >= D) return;
    float m   = sum[j] * invN;
    float var = sq[j] * invN - m * m;
    float aj  = gamma[j] * rsqrtf(var + 1e-5f);
    a[j] = aj;
    c[j] = beta[j] - aj * m;
}

// ------------------- global_add_pool -------------------
__global__ void k_pool(const float* __restrict__ x, const int* __restrict__ batch) {
    int lane = threadIdx.x & 31;
    int w    = (blockIdx.x * blockDim.x + threadIdx.x) >> 5;
    int nW   = (gridDim.x * blockDim.x) >> 5;
    int C    = (NN + nW - 1) / nW;
    int beg = w * C;
    int end = beg + C; if (end > NN) end = NN;
    if (beg >= end) return;

    float a0 = 0, a1 = 0, a2 = 0, a3 = 0, cntf = 0;
    int cur = batch[beg];
    for (int v = beg; v < end; v++) {
        int g = batch[v];
        if (g != cur) {
            atomicAdd(&g_pool[cur * DF + lane * 4 + 0], a0);
            atomicAdd(&g_pool[cur * DF + lane * 4 + 1], a1);
            atomicAdd(&g_pool[cur * DF + lane * 4 + 2], a2);
            atomicAdd(&g_pool[cur * DF + lane * 4 + 3], a3);
            if (lane == 0) atomicAdd(&g_gcnt[cur], cntf);
            a0 = a1 = a2 = a3 = 0.f; cntf = 0.f; cur = g;
        }
        float4 xv = *((const float4*)(x + (size_t)v * DF) + lane);
        a0 += xv.x; a1 += xv.y; a2 += xv.z; a3 += xv.w; cntf += 1.f;
    }
    atomicAdd(&g_pool[cur * DF + lane * 4 + 0], a0);
    atomicAdd(&g_pool[cur * DF + lane * 4 + 1], a1);
    atomicAdd(&g_pool[cur * DF + lane * 4 + 2], a2);
    atomicAdd(&g_pool[cur * DF + lane * 4 + 3], a3);
    if (lane == 0) atomicAdd(&g_gcnt[cur], cntf);
}

// ------------------- head -------------------
__global__ void __launch_bounds__(256) k_hg0(const float* __restrict__ Wh0,
                                             const float* __restrict__ bh0) {
    __shared__ float sx[DF];
    int g = blockIdx.x, j = threadIdx.x;
    if (j < DF) sx[j] = g_affa[j] * g_pool[g * DF + j] + g_affc[j] * g_gcnt[g];
    __syncthreads();
    float acc = bh0[j];
#pragma unroll 8
    for (int k = 0; k < DF; k++) acc = fmaf(sx[k], Wh0[k * DH + j], acc);
    float v = fmaxf(acc, 0.f);
    g_h0[g * DH + j] = v;
    atomicAdd(&g_sq[j], v);
    atomicAdd(&g_sq[DH + j], v * v);
}
__global__ void __launch_bounds__(256) k_hg1(const float* __restrict__ Wh1,
                                             const float* __restrict__ bh1) {
    __shared__ float sx[DH];
    int g = blockIdx.x, j = threadIdx.x;
    sx[j] = g_ha[j] * g_h0[g * DH + j] + g_hc[j];
    __syncthreads();
    float acc = bh1[j];
#pragma unroll 8
    for (int k = 0; k < DH; k++) acc = fmaf(sx[k], Wh1[k * DH + j], acc);
    float v = fmaxf(acc, 0.f);
    g_h1[g * DH + j] = v;
    atomicAdd(&g_sq[2 * DH + j], v);
    atomicAdd(&g_sq[3 * DH + j], v * v);
}
__global__ void __launch_bounds__(256) k_final(const float* __restrict__ Wout,
                                               const float* __restrict__ bout,
                                               float* __restrict__ out) {
    __shared__ float red[DH];
    int g = blockIdx.x, t = threadIdx.x;
    red[t] = (g_ha[t] * g_h1[g * DH + t] + g_hc[t]) * Wout[t];
    __syncthreads();
    for (int o = DH / 2; o > 0; o >>= 1) {
        if (t < o) red[t] += red[t + o];
        __syncthreads();
    }
    if (t == 0) out[g] = red[0] + bout[0];
}

// ------------------- launch -------------------
extern "C" void kernel_launch(void* const* d_in, const int* in_sizes, int n_in,
                              void* d_out, int out_size) {
    const float* x   = (const float*)d_in[0];
    const int*   ei  = (const int*)d_in[1];
    const int*   bat = (const int*)d_in[2];
    const float* Wc  = (const float*)d_in[3];
    const float* bc  = (const float*)d_in[4];
    const float* gc  = (const float*)d_in[5];
    const float* bec = (const float*)d_in[6];
    const float* Wh0 = (const float*)d_in[7];
    const float* bh0 = (const float*)d_in[8];
    const float* gh0 = (const float*)d_in[9];
    const float* beh0= (const float*)d_in[10];
    const float* Wh1 = (const float*)d_in[11];
    const float* bh1 = (const float*)d_in[12];
    const float* gh1 = (const float*)d_in[13];
    const float* beh1= (const float*)d_in[14];
    const float* Wout= (const float*)d_in[15];
    const float* bout= (const float*)d_in[16];
    float* out = (float*)d_out;

    const int* src = ei;
    const int* dst = ei + NE;

    float *p_x0, *p_x1, *p_h, *p_dvec, *p_bnsum, *p_bnsq;
    float *p_affa, *p_affc, *p_sq, *p_ha, *p_hc;
    __nv_bfloat16 *p_Whi, *p_Wlo;
    cudaGetSymbolAddress((void**)&p_x0,   g_x0);
    cudaGetSymbolAddress((void**)&p_x1,   g_x1);
    cudaGetSymbolAddress((void**)&p_h,    g_h);
    cudaGetSymbolAddress((void**)&p_Whi,  g_Whi);
    cudaGetSymbolAddress((void**)&p_Wlo,  g_Wlo);
    cudaGetSymbolAddress((void**)&p_dvec, g_dvec);
    cudaGetSymbolAddress((void**)&p_bnsum,g_bnsum);
    cudaGetSymbolAddress((void**)&p_bnsq, g_bnsq);
    cudaGetSymbolAddress((void**)&p_affa, g_affa);
    cudaGetSymbolAddress((void**)&p_affc, g_affc);
    cudaGetSymbolAddress((void**)&p_sq,   g_sq);
    cudaGetSymbolAddress((void**)&p_ha,   g_ha);
    cudaGetSymbolAddress((void**)&p_hc,   g_hc);

    cudaFuncSetAttribute(k_mmagemm, cudaFuncAttributeMaxDynamicSharedMemorySize, SM_TOT);

    const int T = 256;
    const int gemmBlocks = (NN + 63) / 64;

    // ---- init + CSR build + degree ----
    k_init<<<(INIT_TOT + T - 1) / T, T>>>();
    k_hist<<<(NE + T - 1) / T, T>>>(dst);
    k_dinv<<<(NN + T - 1) / T, T>>>();
    k_scanA<<<SB, 256>>>();
    k_scanB<<<1, 512>>>();
    k_scanC<<<SB, 256>>>();
    k_fill<<<(NE + T - 1) / T, T>>>(src, dst);

    // ---- conv layer 0 ----
    k_wprep<<<65, T>>>(Wc, 0);
    k_mmagemm<<<gemmBlocks, T, SM_TOT>>>(x, p_Whi, p_Wlo, nullptr, p_h, NN);
    k_agg<<<2048, T>>>(p_h, bc, p_x0, p_bnsum, p_bnsq);
    k_bnaff<<<1, DF>>>(p_bnsum, p_bnsq, gc, bec, p_affa, p_affc, DF, 1.0f / NN);

    // ---- conv layer 1 (BN0 folded) ----
    k_wprep<<<65, T>>>(Wc + DF * DF, 1);
    k_mmagemm<<<gemmBlocks, T, SM_TOT>>>(p_x0, p_Whi, p_Wlo, p_dvec, p_h, NN);
    k_agg<<<2048, T>>>(p_h, bc + DF, p_x1, p_bnsum + DF, p_bnsq + DF);
    k_bnaff<<<1, DF>>>(p_bnsum + DF, p_bnsq + DF, gc + DF, bec + DF, p_affa, p_affc, DF, 1.0f / NN);

    // ---- conv layer 2 ----
    k_wprep<<<65, T>>>(Wc + 2 * DF * DF, 1);
    k_mmagemm<<<gemmBlocks, T, SM_TOT>>>(p_x1, p_Whi, p_Wlo, p_dvec, p_h, NN);
    k_agg<<<2048, T>>>(p_h, bc + 2 * DF, p_x0, p_bnsum + 2 * DF, p_bnsq + 2 * DF);
    k_bnaff<<<1, DF>>>(p_bnsum + 2 * DF, p_bnsq + 2 * DF, gc + 2 * DF, bec + 2 * DF, p_affa, p_affc, DF, 1.0f / NN);

    // ---- pool ----
    k_pool<<<128, T>>>(p_x0, bat);

    // ---- head ----
    k_hg0<<<NG, DH>>>(Wh0, bh0);
    k_bnaff<<<1, DH>>>(p_sq, p_sq + DH, gh0, beh0, p_ha, p_hc, DH, 1.0f / NG);
    k_hg1<<<NG, DH>>>(Wh1, bh1);
    k_bnaff<<<1, DH>>>(p_sq + 2 * DH, p_sq + 3 * DH, gh1, beh1, p_ha, p_hc, DH, 1.0f / NG);
    k_final<<<NG, DH>>>(Wout, bout, out);
}